// round 14
// baseline (speedup 1.0000x reference)
#include <cuda_runtime.h>
#include <cuda_bf16.h>
#include <cstdint>

#define BB 8
#define CC 512
#define CI 256
#define NN 3136
#define EPSBN 1e-5f

// ---- scratch (static device globals; no allocations allowed) ----
__device__ __align__(16) float s_f  [BB * NN * NN];            // fp32 scores
__device__ __align__(16) float s_wy [BB * CC * NN];
__device__ float s_mean[CC];
__device__ float s_rstd[CC];

// split-bf16 operands
__device__ __align__(16) __nv_bfloat16 g_xT_hi [BB * NN * CC]; // x^T [B][N][C]
__device__ __align__(16) __nv_bfloat16 g_xT_lo [BB * NN * CC];
__device__ __align__(16) __nv_bfloat16 g_thT_hi[BB * NN * CI];
__device__ __align__(16) __nv_bfloat16 g_thT_lo[BB * NN * CI];
__device__ __align__(16) __nv_bfloat16 g_phT_hi[BB * NN * CI];
__device__ __align__(16) __nv_bfloat16 g_phT_lo[BB * NN * CI];
__device__ __align__(16) __nv_bfloat16 g_g_hi  [BB * CI * NN];
__device__ __align__(16) __nv_bfloat16 g_g_lo  [BB * CI * NN];
__device__ __align__(16) __nv_bfloat16 g_y_hi  [BB * NN * CI]; // y [N][CI]
__device__ __align__(16) __nv_bfloat16 g_y_lo  [BB * NN * CI];
__device__ __align__(16) __nv_bfloat16 g_pf_hi [BB * (size_t)NN * NN];
__device__ __align__(16) __nv_bfloat16 g_pf_lo [BB * (size_t)NN * NN];
// weight splits
__device__ __align__(16) __nv_bfloat16 g_tw_hi[CI * CC], g_tw_lo[CI * CC];
__device__ __align__(16) __nv_bfloat16 g_pw_hi[CI * CC], g_pw_lo[CI * CC];
__device__ __align__(16) __nv_bfloat16 g_gw_hi[CI * CC], g_gw_lo[CI * CC];
__device__ __align__(16) __nv_bfloat16 g_ww_hi[CC * CI], g_ww_lo[CC * CI];

// ============================================================================
// Warp MMA helpers (sm_80+ ISA only — safe on base compute_103 target)
// ============================================================================
__device__ __forceinline__ uint32_t smem_u32(const void* p) {
    uint32_t a;
    asm("{ .reg .u64 t; cvta.to.shared.u64 t, %1; cvt.u32.u64 %0, t; }"
        : "=r"(a) : "l"(p));
    return a;
}
__device__ __forceinline__ void ldmx4(uint32_t* r, uint32_t addr) {
    asm volatile("ldmatrix.sync.aligned.m8n8.x4.shared.b16 {%0,%1,%2,%3}, [%4];"
                 : "=r"(r[0]), "=r"(r[1]), "=r"(r[2]), "=r"(r[3]) : "r"(addr));
}
__device__ __forceinline__ void mma16816(float* d, const uint32_t* a,
                                         uint32_t b0, uint32_t b1) {
    asm volatile("mma.sync.aligned.m16n8k16.row.col.f32.bf16.bf16.f32 "
                 "{%0,%1,%2,%3}, {%4,%5,%6,%7}, {%8,%9}, {%0,%1,%2,%3};"
                 : "+f"(d[0]), "+f"(d[1]), "+f"(d[2]), "+f"(d[3])
                 : "r"(a[0]), "r"(a[1]), "r"(a[2]), "r"(a[3]), "r"(b0), "r"(b1));
}
__device__ __forceinline__ void cp16(uint32_t saddr, const void* gaddr, uint32_t srcsz) {
    asm volatile("cp.async.cg.shared.global [%0], [%1], 16, %2;"
                 :: "r"(saddr), "l"(gaddr), "r"(srcsz) : "memory");
}
__device__ __forceinline__ void split_bf(float v, __nv_bfloat16& h, __nv_bfloat16& l) {
    h = __float2bfloat16(v);
    l = __float2bfloat16(v - __bfloat162float(h));
}

// ============================================================================
// HMMA split-bf16 GEMM: C[m][n] = sum_k A(m,k)*B(n,k), A [Mg x K], B [Ng x K]
// row-major bf16 hi/lo pairs. Block 128(M) x 256(N), Kc=64, 2-stage cp.async.
// 8 warps as 2(M) x 4(N); warp tile 64x64 (128 fp32 accum / thread).
// OUTM: 0 = fp32 C;  1 = split bf16 (Chi, Clo)
// BIASM: 0 none; 1 bias[m] (row); 2 bias[n] (col)
// ============================================================================
#define KC 64
#define A_T 16384                    // 128x64 bf16
#define B_T 32768                    // 256x64 bf16
#define STG (2 * A_T + 2 * B_T)      // 98304: AH, AL, BH, BL
#define MMA_SMEM (2 * STG)           // 196608

__device__ __forceinline__ uint32_t sw_off(int row, int chunk) {
    return (uint32_t)(row * 128 + ((chunk ^ (row & 7)) << 4));
}

__device__ __forceinline__ void stage_load(
    uint32_t st_base,
    const __nv_bfloat16* Ahi, const __nv_bfloat16* Alo,
    const __nv_bfloat16* Bhi, const __nv_bfloat16* Blo,
    int m0, int n0, int Mg, int Ng, int K, int k0, int tid)
{
    const int row = tid >> 1;          // 0..127
    const int cb = (tid & 1) * 4;      // chunk base 0 or 4
    // A tile: 128 rows
    {
        const int gr = m0 + row;
        const uint32_t vsz = (gr < Mg) ? 16u : 0u;
        const int r = (gr < Mg) ? gr : 0;
        const __nv_bfloat16* sh = Ahi + (size_t)r * K + k0 + cb * 8;
        const __nv_bfloat16* sl = Alo + (size_t)r * K + k0 + cb * 8;
#pragma unroll
        for (int i = 0; i < 4; ++i) {
            uint32_t o = sw_off(row, cb + i);
            cp16(st_base + o,       sh + i * 8, vsz);
            cp16(st_base + A_T + o, sl + i * 8, vsz);
        }
    }
    // B tile: 256 rows in two passes
#pragma unroll
    for (int p = 0; p < 2; ++p) {
        const int rowb = row + p * 128;
        const int gr = n0 + rowb;
        const uint32_t vsz = (gr < Ng) ? 16u : 0u;
        const int r = (gr < Ng) ? gr : 0;
        const __nv_bfloat16* sh = Bhi + (size_t)r * K + k0 + cb * 8;
        const __nv_bfloat16* sl = Blo + (size_t)r * K + k0 + cb * 8;
#pragma unroll
        for (int i = 0; i < 4; ++i) {
            uint32_t o = sw_off(rowb, cb + i);
            cp16(st_base + 2 * A_T + o,       sh + i * 8, vsz);
            cp16(st_base + 2 * A_T + B_T + o, sl + i * 8, vsz);
        }
    }
}

template <int OUTM, int BIASM>
__global__ void __launch_bounds__(256, 1) mma_gemm(
    const __nv_bfloat16* __restrict__ Ahi, const __nv_bfloat16* __restrict__ Alo,
    const __nv_bfloat16* __restrict__ Bhi, const __nv_bfloat16* __restrict__ Blo,
    float* __restrict__ Cf,
    __nv_bfloat16* __restrict__ Chi, __nv_bfloat16* __restrict__ Clo,
    const float* __restrict__ bias,
    int Mg, int Ng, int K,
    long long sA, long long sB, long long sC)
{
    extern __shared__ char smem[];
    const int tid = threadIdx.x;
    const int lane = tid & 31, wid = tid >> 5;
    const int m0 = blockIdx.y * 128, n0 = blockIdx.x * 256;
    Ahi += (size_t)blockIdx.z * sA;  Alo += (size_t)blockIdx.z * sA;
    Bhi += (size_t)blockIdx.z * sB;  Blo += (size_t)blockIdx.z * sB;
    const uint32_t sb = smem_u32(smem);

    const int wm = (wid & 1) * 64;       // warp m offset (0/64)
    const int wn = (wid >> 1) * 64;      // warp n offset (0/64/128/192)
    const int gi = lane >> 3, rin = lane & 7;

    float acc[4][8][4];
#pragma unroll
    for (int a = 0; a < 4; ++a)
#pragma unroll
        for (int b = 0; b < 8; ++b)
#pragma unroll
            for (int c = 0; c < 4; ++c) acc[a][b][c] = 0.f;

    const int nkc = K / KC;
    stage_load(sb, Ahi, Alo, Bhi, Blo, m0, n0, Mg, Ng, K, 0, tid);
    asm volatile("cp.async.commit_group;" ::: "memory");

    for (int cchunk = 0; cchunk < nkc; ++cchunk) {
        if (cchunk + 1 < nkc) {
            stage_load(sb + ((cchunk + 1) & 1) * STG, Ahi, Alo, Bhi, Blo,
                       m0, n0, Mg, Ng, K, (cchunk + 1) * KC, tid);
            asm volatile("cp.async.commit_group;" ::: "memory");
            asm volatile("cp.async.wait_group 1;" ::: "memory");
        } else {
            asm volatile("cp.async.wait_group 0;" ::: "memory");
        }
        __syncthreads();

        const uint32_t stB = sb + (cchunk & 1) * STG;
#pragma unroll
        for (int ks = 0; ks < 4; ++ks) {
            uint32_t Ah[4][4], Al[4][4];
#pragma unroll
            for (int mt = 0; mt < 4; ++mt) {
                const int rowA = wm + mt * 16 + (gi & 1) * 8 + rin;
                const int chA = ks * 2 + (gi >> 1);
                const uint32_t aaddr = stB + sw_off(rowA, chA);
                ldmx4(Ah[mt], aaddr);
                ldmx4(Al[mt], aaddr + A_T);
            }
#pragma unroll
            for (int np = 0; np < 4; ++np) {
                const int rowB = wn + np * 16 + (gi >> 1) * 8 + rin;
                const int chB = ks * 2 + (gi & 1);
                const uint32_t baddr = stB + 2 * A_T + sw_off(rowB, chB);
                uint32_t Bh[4], Bl[4];
                ldmx4(Bh, baddr);
                ldmx4(Bl, baddr + B_T);
#pragma unroll
                for (int mt = 0; mt < 4; ++mt) {
                    mma16816(acc[mt][np * 2],     Ah[mt], Bh[0], Bh[1]);
                    mma16816(acc[mt][np * 2],     Al[mt], Bh[0], Bh[1]);
                    mma16816(acc[mt][np * 2],     Ah[mt], Bl[0], Bl[1]);
                    mma16816(acc[mt][np * 2 + 1], Ah[mt], Bh[2], Bh[3]);
                    mma16816(acc[mt][np * 2 + 1], Al[mt], Bh[2], Bh[3]);
                    mma16816(acc[mt][np * 2 + 1], Ah[mt], Bl[2], Bl[3]);
                }
            }
        }
        __syncthreads();
    }

    // ---- epilogue ----
    const int g = lane >> 2, tg = lane & 3;
#pragma unroll
    for (int mt = 0; mt < 4; ++mt) {
#pragma unroll
        for (int nt = 0; nt < 8; ++nt) {
            const int row0 = m0 + wm + mt * 16 + g;
            const int col = n0 + wn + nt * 8 + tg * 2;
            if (col >= Ng) continue;
            float bc0 = 0.f, bc1 = 0.f;
            if (BIASM == 2) { bc0 = bias[col]; bc1 = bias[col + 1]; }
#pragma unroll
            for (int h = 0; h < 2; ++h) {
                const int row = row0 + h * 8;
                if (row >= Mg) continue;
                float v0 = acc[mt][nt][h * 2], v1 = acc[mt][nt][h * 2 + 1];
                if (BIASM == 1) { float bv = bias[row]; v0 += bv; v1 += bv; }
                if (BIASM == 2) { v0 += bc0; v1 += bc1; }
                const size_t off = (size_t)blockIdx.z * sC + (size_t)row * Ng + col;
                if (OUTM == 0) {
                    float2 v; v.x = v0; v.y = v1;
                    *(float2*)(Cf + off) = v;
                } else {
                    __nv_bfloat16 h0, l0, h1, l1;
                    split_bf(v0, h0, l0); split_bf(v1, h1, l1);
                    __nv_bfloat162 hp; hp.x = h0; hp.y = h1;
                    __nv_bfloat162 lp; lp.x = l0; lp.y = l1;
                    *(__nv_bfloat162*)(Chi + off) = hp;
                    *(__nv_bfloat162*)(Clo + off) = lp;
                }
            }
        }
    }
}

// ============================================================================
// x: [B][CD][NN] fp32 -> [B][NN][CD] split bf16 (transpose + split), CD param
// ============================================================================
__global__ __launch_bounds__(256) void split_T_kernel(
    const float* __restrict__ in,
    __nv_bfloat16* __restrict__ ohi, __nv_bfloat16* __restrict__ olo, int CD)
{
    __shared__ float t[32][33];
    const int b = blockIdx.z;
    const int n0 = blockIdx.x * 32, c0 = blockIdx.y * 32;
    const float* src = in + (size_t)b * CD * NN;
    const int tx = threadIdx.x & 31, ty = threadIdx.x >> 5;
#pragma unroll
    for (int r = 0; r < 4; ++r)
        t[ty + r * 8][tx] = src[(size_t)(c0 + ty + r * 8) * NN + n0 + tx];
    __syncthreads();
    __nv_bfloat16* dhi = ohi + (size_t)b * NN * CD;
    __nv_bfloat16* dlo = olo + (size_t)b * NN * CD;
#pragma unroll
    for (int r = 0; r < 4; ++r) {
        float v = t[tx][ty + r * 8];
        __nv_bfloat16 h, l; split_bf(v, h, l);
        size_t o = (size_t)(n0 + ty + r * 8) * CD + c0 + tx;
        dhi[o] = h; dlo[o] = l;
    }
}

// elementwise split (weights)
__global__ __launch_bounds__(256) void split4_kernel(
    const float* __restrict__ in,
    __nv_bfloat16* __restrict__ ohi, __nv_bfloat16* __restrict__ olo, size_t n4)
{
    size_t i = (size_t)blockIdx.x * 256 + threadIdx.x;
    if (i >= n4) return;
    float4 v = ((const float4*)in)[i];
    __nv_bfloat16 h0, l0, h1, l1, h2, l2, h3, l3;
    split_bf(v.x, h0, l0); split_bf(v.y, h1, l1);
    split_bf(v.z, h2, l2); split_bf(v.w, h3, l3);
    __nv_bfloat162 hp0; hp0.x = h0; hp0.y = h1;
    __nv_bfloat162 hp1; hp1.x = h2; hp1.y = h3;
    __nv_bfloat162 lp0; lp0.x = l0; lp0.y = l1;
    __nv_bfloat162 lp1; lp1.x = l2; lp1.y = l3;
    ((__nv_bfloat162*)ohi)[i * 2]     = hp0;
    ((__nv_bfloat162*)ohi)[i * 2 + 1] = hp1;
    ((__nv_bfloat162*)olo)[i * 2]     = lp0;
    ((__nv_bfloat162*)olo)[i * 2 + 1] = lp1;
}

// ============================================================================
// Row softmax over f (fp32 in) -> split bf16 probabilities out
// ============================================================================
__global__ __launch_bounds__(256) void softmax_kernel(
    const float* __restrict__ f,
    __nv_bfloat16* __restrict__ pf_hi, __nv_bfloat16* __restrict__ pf_lo)
{
    __shared__ float4 buf[NN / 4];
    __shared__ float red[8];
    const float* row = f + (size_t)blockIdx.x * NN;
    __nv_bfloat16* rh = pf_hi + (size_t)blockIdx.x * NN;
    __nv_bfloat16* rl = pf_lo + (size_t)blockIdx.x * NN;
    const int tid = threadIdx.x;

    float mx = -1e30f;
    for (int i = tid; i < NN / 4; i += 256) {
        float4 v = *(const float4*)(row + i * 4);
        buf[i] = v;
        mx = fmaxf(mx, fmaxf(fmaxf(v.x, v.y), fmaxf(v.z, v.w)));
    }
#pragma unroll
    for (int o = 16; o > 0; o >>= 1) mx = fmaxf(mx, __shfl_xor_sync(0xffffffffu, mx, o));
    if ((tid & 31) == 0) red[tid >> 5] = mx;
    __syncthreads();
    if (tid == 0) {
        float v = red[0];
        for (int i = 1; i < 8; ++i) v = fmaxf(v, red[i]);
        red[0] = v;
    }
    __syncthreads();
    mx = red[0];
    __syncthreads();

    float sum = 0.f;
    for (int i = tid; i < NN / 4; i += 256) {
        float4 v = buf[i];
        v.x = __expf(v.x - mx); v.y = __expf(v.y - mx);
        v.z = __expf(v.z - mx); v.w = __expf(v.w - mx);
        buf[i] = v;
        sum += v.x + v.y + v.z + v.w;
    }
#pragma unroll
    for (int o = 16; o > 0; o >>= 1) sum += __shfl_xor_sync(0xffffffffu, sum, o);
    if ((tid & 31) == 0) red[tid >> 5] = sum;
    __syncthreads();
    if (tid == 0) {
        float v = 0.f;
        for (int i = 0; i < 8; ++i) v += red[i];
        red[0] = v;
    }
    __syncthreads();
    const float inv = 1.f / red[0];

    for (int i = tid; i < NN / 4; i += 256) {
        float4 v = buf[i];
        v.x *= inv; v.y *= inv; v.z *= inv; v.w *= inv;
        __nv_bfloat16 h0, l0, h1, l1, h2, l2, h3, l3;
        split_bf(v.x, h0, l0); split_bf(v.y, h1, l1);
        split_bf(v.z, h2, l2); split_bf(v.w, h3, l3);
        __nv_bfloat162 hp0; hp0.x = h0; hp0.y = h1;
        __nv_bfloat162 hp1; hp1.x = h2; hp1.y = h3;
        __nv_bfloat162 lp0; lp0.x = l0; lp0.y = l1;
        __nv_bfloat162 lp1; lp1.x = l2; lp1.y = l3;
        ((__nv_bfloat162*)rh)[i * 2]     = hp0;
        ((__nv_bfloat162*)rh)[i * 2 + 1] = hp1;
        ((__nv_bfloat162*)rl)[i * 2]     = lp0;
        ((__nv_bfloat162*)rl)[i * 2 + 1] = lp1;
    }
}

// ============================================================================
// BatchNorm stats + finalize
// ============================================================================
__global__ __launch_bounds__(256) void bnstats_kernel(const float* __restrict__ wy)
{
    const int c = blockIdx.x;
    const int tid = threadIdx.x;
    float s = 0.f, s2 = 0.f;
    for (int b = 0; b < BB; ++b) {
        const float* row = wy + ((size_t)b * CC + c) * NN;
        for (int i = tid; i < NN / 4; i += 256) {
            float4 v = *(const float4*)(row + i * 4);
            s  += v.x + v.y + v.z + v.w;
            s2 += v.x * v.x + v.y * v.y + v.z * v.z + v.w * v.w;
        }
    }
#pragma unroll
    for (int o = 16; o > 0; o >>= 1) {
        s  += __shfl_xor_sync(0xffffffffu, s, o);
        s2 += __shfl_xor_sync(0xffffffffu, s2, o);
    }
    __shared__ float rs[8], rs2[8];
    if ((tid & 31) == 0) { rs[tid >> 5] = s; rs2[tid >> 5] = s2; }
    __syncthreads();
    if (tid == 0) {
        float ts = 0.f, ts2 = 0.f;
        for (int i = 0; i < 8; ++i) { ts += rs[i]; ts2 += rs2[i]; }
        const float cnt = (float)(BB * NN);
        const float mean = ts / cnt;
        const float var = ts2 / cnt - mean * mean;
        s_mean[c] = mean;
        s_rstd[c] = rsqrtf(var + EPSBN);
    }
}

__global__ __launch_bounds__(256) void bn_finalize_kernel(
    const float* __restrict__ wy, const float* __restrict__ x,
    const float* __restrict__ gamma, const float* __restrict__ beta,
    float* __restrict__ out)
{
    const size_t i4 = (size_t)blockIdx.x * 256 + threadIdx.x;
    const size_t total4 = (size_t)BB * CC * NN / 4;
    if (i4 >= total4) return;
    const size_t i = i4 * 4;
    const int c = (int)((i / NN) % CC);
    float4 w  = *(const float4*)(wy + i);
    float4 xv = *(const float4*)(x + i);
    const float m = s_mean[c], r = s_rstd[c];
    const float gm = gamma[c], bt = beta[c];
    float4 o;
    o.x = (w.x - m) * r * gm + bt + xv.x;
    o.y = (w.y - m) * r * gm + bt + xv.y;
    o.z = (w.z - m) * r * gm + bt + xv.z;
    o.w = (w.w - m) * r * gm + bt + xv.w;
    *(float4*)(out + i) = o;
}

// ============================================================================
// Launch
// ============================================================================
extern "C" void kernel_launch(void* const* d_in, const int* in_sizes, int n_in,
                              void* d_out, int out_size)
{
    (void)in_sizes; (void)n_in; (void)out_size;
    const float* x       = (const float*)d_in[0];
    const float* theta_w = (const float*)d_in[1];
    const float* theta_b = (const float*)d_in[2];
    const float* phi_w   = (const float*)d_in[3];
    const float* phi_b   = (const float*)d_in[4];
    const float* g_w     = (const float*)d_in[5];
    const float* g_b     = (const float*)d_in[6];
    const float* w_w     = (const float*)d_in[7];
    const float* w_b     = (const float*)d_in[8];
    const float* gamma   = (const float*)d_in[9];
    const float* beta    = (const float*)d_in[10];
    float* out = (float*)d_out;

    float *p_f, *p_wy;
    __nv_bfloat16 *p_xT_hi, *p_xT_lo, *p_thT_hi, *p_thT_lo, *p_phT_hi, *p_phT_lo;
    __nv_bfloat16 *p_g_hi, *p_g_lo, *p_y_hi, *p_y_lo, *p_pf_hi, *p_pf_lo;
    __nv_bfloat16 *p_tw_hi, *p_tw_lo, *p_pw_hi, *p_pw_lo, *p_gw_hi, *p_gw_lo, *p_ww_hi, *p_ww_lo;
    cudaGetSymbolAddress((void**)&p_f,      s_f);
    cudaGetSymbolAddress((void**)&p_wy,     s_wy);
    cudaGetSymbolAddress((void**)&p_xT_hi,  g_xT_hi);
    cudaGetSymbolAddress((void**)&p_xT_lo,  g_xT_lo);
    cudaGetSymbolAddress((void**)&p_thT_hi, g_thT_hi);
    cudaGetSymbolAddress((void**)&p_thT_lo, g_thT_lo);
    cudaGetSymbolAddress((void**)&p_phT_hi, g_phT_hi);
    cudaGetSymbolAddress((void**)&p_phT_lo, g_phT_lo);
    cudaGetSymbolAddress((void**)&p_g_hi,   g_g_hi);
    cudaGetSymbolAddress((void**)&p_g_lo,   g_g_lo);
    cudaGetSymbolAddress((void**)&p_y_hi,   g_y_hi);
    cudaGetSymbolAddress((void**)&p_y_lo,   g_y_lo);
    cudaGetSymbolAddress((void**)&p_pf_hi,  g_pf_hi);
    cudaGetSymbolAddress((void**)&p_pf_lo,  g_pf_lo);
    cudaGetSymbolAddress((void**)&p_tw_hi,  g_tw_hi);
    cudaGetSymbolAddress((void**)&p_tw_lo,  g_tw_lo);
    cudaGetSymbolAddress((void**)&p_pw_hi,  g_pw_hi);
    cudaGetSymbolAddress((void**)&p_pw_lo,  g_pw_lo);
    cudaGetSymbolAddress((void**)&p_gw_hi,  g_gw_hi);
    cudaGetSymbolAddress((void**)&p_gw_lo,  g_gw_lo);
    cudaGetSymbolAddress((void**)&p_ww_hi,  g_ww_hi);
    cudaGetSymbolAddress((void**)&p_ww_lo,  g_ww_lo);

    cudaFuncSetAttribute(mma_gemm<0, 0>, cudaFuncAttributeMaxDynamicSharedMemorySize, MMA_SMEM);
    cudaFuncSetAttribute(mma_gemm<0, 1>, cudaFuncAttributeMaxDynamicSharedMemorySize, MMA_SMEM);
    cudaFuncSetAttribute(mma_gemm<1, 0>, cudaFuncAttributeMaxDynamicSharedMemorySize, MMA_SMEM);
    cudaFuncSetAttribute(mma_gemm<1, 1>, cudaFuncAttributeMaxDynamicSharedMemorySize, MMA_SMEM);
    cudaFuncSetAttribute(mma_gemm<1, 2>, cudaFuncAttributeMaxDynamicSharedMemorySize, MMA_SMEM);

    const dim3 blk(256);
    const long long sXT = (long long)NN * CC;
    const long long sP  = (long long)CI * NN;   // == NN*CI
    const long long sF  = (long long)NN * NN;

    // 0) operand conversions
    const dim3 gxT(NN / 32, CC / 32, BB);       // (98, 16, 8)
    split_T_kernel<<<gxT, blk>>>(x, p_xT_hi, p_xT_lo, CC);
    const size_t nw4 = (size_t)CI * CC / 4;
    split4_kernel<<<(unsigned)((nw4 + 255) / 256), blk>>>(theta_w, p_tw_hi, p_tw_lo, nw4);
    split4_kernel<<<(unsigned)((nw4 + 255) / 256), blk>>>(phi_w,   p_pw_hi, p_pw_lo, nw4);
    split4_kernel<<<(unsigned)((nw4 + 255) / 256), blk>>>(g_w,     p_gw_hi, p_gw_lo, nw4);
    split4_kernel<<<(unsigned)((nw4 + 255) / 256), blk>>>(w_w,     p_ww_hi, p_ww_lo, nw4);

    // 1) projections (HMMA, split-bf16 out, bias fused)
    //    theta/phi: [NN][CI] = xT @ w^T   (col bias); N=256 -> 1 block col
    const dim3 gth(1, (NN + 127) / 128, BB);          // (1, 25, 8)
    mma_gemm<1, 2><<<gth, blk, MMA_SMEM>>>(p_xT_hi, p_xT_lo, p_tw_hi, p_tw_lo,
        nullptr, p_thT_hi, p_thT_lo, theta_b, NN, CI, CC, sXT, 0, sP);
    mma_gemm<1, 2><<<gth, blk, MMA_SMEM>>>(p_xT_hi, p_xT_lo, p_pw_hi, p_pw_lo,
        nullptr, p_phT_hi, p_phT_lo, phi_b, NN, CI, CC, sXT, 0, sP);
    //    g: [CI][NN] = g_w @ x   (row bias)
    const dim3 gg((NN + 255) / 256, CI / 128, BB);    // (13, 2, 8)
    mma_gemm<1, 1><<<gg, blk, MMA_SMEM>>>(p_gw_hi, p_gw_lo, p_xT_hi, p_xT_lo,
        nullptr, p_g_hi, p_g_lo, g_b, CI, NN, CC, 0, sXT, sP);

    // 2) f[n][m] = thT[n] . phT[m]   (HMMA, fp32 out)
    const dim3 gf((NN + 255) / 256, (NN + 127) / 128, BB);   // (13, 25, 8)
    mma_gemm<0, 0><<<gf, blk, MMA_SMEM>>>(p_thT_hi, p_thT_lo, p_phT_hi, p_phT_lo,
        p_f, nullptr, nullptr, nullptr, NN, NN, CI, sP, sP, sF);

    // 3) softmax -> split-bf16 probabilities
    softmax_kernel<<<BB * NN, blk>>>(p_f, p_pf_hi, p_pf_lo);

    // 4) y[n][c] = Pf[n] . g[c]      (HMMA, split-bf16 out; N=256 -> Pf read once)
    const dim3 gy(1, (NN + 127) / 128, BB);           // (1, 25, 8)
    mma_gemm<1, 0><<<gy, blk, MMA_SMEM>>>(p_pf_hi, p_pf_lo, p_g_hi, p_g_lo,
        nullptr, p_y_hi, p_y_lo, nullptr, NN, CI, NN, sF, sP, sP);

    // 5) wy[o][n] = w_w[o] . y[n]    (HMMA, fp32 out, row bias)
    const dim3 gw((NN + 255) / 256, CC / 128, BB);    // (13, 4, 8)
    mma_gemm<0, 1><<<gw, blk, MMA_SMEM>>>(p_ww_hi, p_ww_lo, p_y_hi, p_y_lo,
        p_wy, nullptr, nullptr, w_b, CC, NN, CI, 0, sP, (long long)CC * NN);

    // 6) BN stats + finalize with residual
    bnstats_kernel<<<CC, blk>>>(p_wy);
    bn_finalize_kernel<<<(unsigned)((size_t)BB * CC * NN / 4 / 256), blk>>>(p_wy, x, gamma, beta, out);
}

// round 15
// speedup vs baseline: 1.2616x; 1.2616x over previous
#include <cuda_runtime.h>
#include <cuda_bf16.h>
#include <cuda_fp16.h>
#include <cstdint>

#define BB 8
#define CC 512
#define CI 256
#define NN 3136
#define EPSBN 1e-5f
#define PF_SCALE 16384.0f

// ---- scratch (static device globals; no allocations allowed) ----
__device__ __align__(16) float s_f  [BB * NN * NN];            // fp32 scores
__device__ __align__(16) float s_wy [BB * CC * NN];
__device__ float s_mean[CC];
__device__ float s_rstd[CC];

// bf16 split operands (projection inputs + W path)
__device__ __align__(16) __nv_bfloat16 g_xT_hi [BB * NN * CC];
__device__ __align__(16) __nv_bfloat16 g_xT_lo [BB * NN * CC];
__device__ __align__(16) __nv_bfloat16 g_y_hi  [BB * NN * CI];
__device__ __align__(16) __nv_bfloat16 g_y_lo  [BB * NN * CI];
__device__ __align__(16) __nv_bfloat16 g_tw_hi[CI * CC], g_tw_lo[CI * CC];
__device__ __align__(16) __nv_bfloat16 g_pw_hi[CI * CC], g_pw_lo[CI * CC];
__device__ __align__(16) __nv_bfloat16 g_gw_hi[CI * CC], g_gw_lo[CI * CC];
__device__ __align__(16) __nv_bfloat16 g_ww_hi[CC * CI], g_ww_lo[CC * CI];

// fp16 split operands (attention path)
__device__ __align__(16) __half g_thT_hi[BB * NN * CI];
__device__ __align__(16) __half g_thT_lo[BB * NN * CI];
__device__ __align__(16) __half g_phT_hi[BB * NN * CI];
__device__ __align__(16) __half g_phT_lo[BB * NN * CI];
__device__ __align__(16) __half g_gp_hi [BB * CI * NN];
__device__ __align__(16) __half g_gp_lo [BB * CI * NN];
__device__ __align__(16) __half g_pf_hi [BB * (size_t)NN * NN];
__device__ __align__(16) __half g_pf_lo [BB * (size_t)NN * NN];

// ============================================================================
// Warp MMA helpers (sm_80+ ISA only)
// ============================================================================
__device__ __forceinline__ uint32_t smem_u32(const void* p) {
    uint32_t a;
    asm("{ .reg .u64 t; cvta.to.shared.u64 t, %1; cvt.u32.u64 %0, t; }"
        : "=r"(a) : "l"(p));
    return a;
}
__device__ __forceinline__ void ldmx4(uint32_t* r, uint32_t addr) {
    asm volatile("ldmatrix.sync.aligned.m8n8.x4.shared.b16 {%0,%1,%2,%3}, [%4];"
                 : "=r"(r[0]), "=r"(r[1]), "=r"(r[2]), "=r"(r[3]) : "r"(addr));
}
__device__ __forceinline__ void mma16816(float* d, const uint32_t* a,
                                         uint32_t b0, uint32_t b1) {
    asm volatile("mma.sync.aligned.m16n8k16.row.col.f32.bf16.bf16.f32 "
                 "{%0,%1,%2,%3}, {%4,%5,%6,%7}, {%8,%9}, {%0,%1,%2,%3};"
                 : "+f"(d[0]), "+f"(d[1]), "+f"(d[2]), "+f"(d[3])
                 : "r"(a[0]), "r"(a[1]), "r"(a[2]), "r"(a[3]), "r"(b0), "r"(b1));
}
__device__ __forceinline__ void mma16816h(float* d, const uint32_t* a,
                                          uint32_t b0, uint32_t b1) {
    asm volatile("mma.sync.aligned.m16n8k16.row.col.f32.f16.f16.f32 "
                 "{%0,%1,%2,%3}, {%4,%5,%6,%7}, {%8,%9}, {%0,%1,%2,%3};"
                 : "+f"(d[0]), "+f"(d[1]), "+f"(d[2]), "+f"(d[3])
                 : "r"(a[0]), "r"(a[1]), "r"(a[2]), "r"(a[3]), "r"(b0), "r"(b1));
}
__device__ __forceinline__ void cp16(uint32_t saddr, const void* gaddr, uint32_t srcsz) {
    asm volatile("cp.async.cg.shared.global [%0], [%1], 16, %2;"
                 :: "r"(saddr), "l"(gaddr), "r"(srcsz) : "memory");
}
__device__ __forceinline__ void split_bf(float v, __nv_bfloat16& h, __nv_bfloat16& l) {
    h = __float2bfloat16(v);
    l = __float2bfloat16(v - __bfloat162float(h));
}
__device__ __forceinline__ void split_h(float v, __half& h, __half& l) {
    h = __float2half(v);
    l = __float2half(v - __half2float(h));
}

#define KC 64
#define A_T 16384                    // one 128x64 16-bit tile
#define STG (4 * A_T)                // bf16 engine stage: AH, AL, BH, BL
#define MMA_SMEM (2 * STG)           // 131072
#define STG2 (3 * A_T)               // h2 engine stage: AH, AL, BH
#define MMA_SMEM2 (2 * STG2)         // 98304

__device__ __forceinline__ uint32_t sw_off(int row, int chunk) {
    return (uint32_t)(row * 128 + ((chunk ^ (row & 7)) << 4));
}

// ============================================================================
// bf16 3-term engine: block 128x128, warps 4(M)x2(N), warp tile 32x64.
// OUTM: 0 = fp32; 1 = bf16 split; 2 = fp16 split.  BIASM: 0/1(row)/2(col)
// ============================================================================
__device__ __forceinline__ void stage_load_bf(
    uint32_t st_base,
    const __nv_bfloat16* Ahi, const __nv_bfloat16* Alo,
    const __nv_bfloat16* Bhi, const __nv_bfloat16* Blo,
    int m0, int n0, int Mg, int Ng, int K, int k0, int tid)
{
    const int row = tid >> 1;
    const int cb = (tid & 1) * 4;
    {
        const int gr = m0 + row;
        const uint32_t vsz = (gr < Mg) ? 16u : 0u;
        const int r = (gr < Mg) ? gr : 0;
        const __nv_bfloat16* sh = Ahi + (size_t)r * K + k0 + cb * 8;
        const __nv_bfloat16* sl = Alo + (size_t)r * K + k0 + cb * 8;
#pragma unroll
        for (int i = 0; i < 4; ++i) {
            uint32_t o = sw_off(row, cb + i);
            cp16(st_base + o,       sh + i * 8, vsz);
            cp16(st_base + A_T + o, sl + i * 8, vsz);
        }
    }
    {
        const int gr = n0 + row;
        const uint32_t vsz = (gr < Ng) ? 16u : 0u;
        const int r = (gr < Ng) ? gr : 0;
        const __nv_bfloat16* sh = Bhi + (size_t)r * K + k0 + cb * 8;
        const __nv_bfloat16* sl = Blo + (size_t)r * K + k0 + cb * 8;
#pragma unroll
        for (int i = 0; i < 4; ++i) {
            uint32_t o = sw_off(row, cb + i);
            cp16(st_base + 2 * A_T + o, sh + i * 8, vsz);
            cp16(st_base + 3 * A_T + o, sl + i * 8, vsz);
        }
    }
}

template <int OUTM, int BIASM>
__global__ void __launch_bounds__(256, 1) mma_gemm(
    const __nv_bfloat16* __restrict__ Ahi, const __nv_bfloat16* __restrict__ Alo,
    const __nv_bfloat16* __restrict__ Bhi, const __nv_bfloat16* __restrict__ Blo,
    float* __restrict__ Cf, void* __restrict__ ChiV, void* __restrict__ CloV,
    const float* __restrict__ bias,
    int Mg, int Ng, int K,
    long long sA, long long sB, long long sC)
{
    extern __shared__ char smem[];
    const int tid = threadIdx.x;
    const int lane = tid & 31, wid = tid >> 5;
    const int m0 = blockIdx.y * 128, n0 = blockIdx.x * 128;
    Ahi += (size_t)blockIdx.z * sA;  Alo += (size_t)blockIdx.z * sA;
    Bhi += (size_t)blockIdx.z * sB;  Blo += (size_t)blockIdx.z * sB;
    const uint32_t sb = smem_u32(smem);

    const int wm = (wid >> 1) * 32;
    const int wn = (wid & 1) * 64;
    const int gi = lane >> 3, rin = lane & 7;

    float acc[2][8][4];
#pragma unroll
    for (int a = 0; a < 2; ++a)
#pragma unroll
        for (int b = 0; b < 8; ++b)
#pragma unroll
            for (int c = 0; c < 4; ++c) acc[a][b][c] = 0.f;

    const int nkc = K / KC;
    stage_load_bf(sb, Ahi, Alo, Bhi, Blo, m0, n0, Mg, Ng, K, 0, tid);
    asm volatile("cp.async.commit_group;" ::: "memory");

    for (int cc = 0; cc < nkc; ++cc) {
        if (cc + 1 < nkc) {
            stage_load_bf(sb + ((cc + 1) & 1) * STG, Ahi, Alo, Bhi, Blo,
                          m0, n0, Mg, Ng, K, (cc + 1) * KC, tid);
            asm volatile("cp.async.commit_group;" ::: "memory");
            asm volatile("cp.async.wait_group 1;" ::: "memory");
        } else {
            asm volatile("cp.async.wait_group 0;" ::: "memory");
        }
        __syncthreads();

        const uint32_t stB = sb + (cc & 1) * STG;
#pragma unroll
        for (int ks = 0; ks < 4; ++ks) {
            uint32_t Ah[2][4], Al[2][4];
#pragma unroll
            for (int mt = 0; mt < 2; ++mt) {
                const int rowA = wm + mt * 16 + (gi & 1) * 8 + rin;
                const int chA = ks * 2 + (gi >> 1);
                const uint32_t aaddr = stB + sw_off(rowA, chA);
                ldmx4(Ah[mt], aaddr);
                ldmx4(Al[mt], aaddr + A_T);
            }
#pragma unroll
            for (int np = 0; np < 4; ++np) {
                const int rowB = wn + np * 16 + (gi >> 1) * 8 + rin;
                const int chB = ks * 2 + (gi & 1);
                const uint32_t baddr = stB + 2 * A_T + sw_off(rowB, chB);
                uint32_t Bh[4], Bl[4];
                ldmx4(Bh, baddr);
                ldmx4(Bl, baddr + A_T);
#pragma unroll
                for (int mt = 0; mt < 2; ++mt) {
                    mma16816(acc[mt][np * 2],     Ah[mt], Bh[0], Bh[1]);
                    mma16816(acc[mt][np * 2],     Al[mt], Bh[0], Bh[1]);
                    mma16816(acc[mt][np * 2],     Ah[mt], Bl[0], Bl[1]);
                    mma16816(acc[mt][np * 2 + 1], Ah[mt], Bh[2], Bh[3]);
                    mma16816(acc[mt][np * 2 + 1], Al[mt], Bh[2], Bh[3]);
                    mma16816(acc[mt][np * 2 + 1], Ah[mt], Bl[2], Bl[3]);
                }
            }
        }
        __syncthreads();
    }

    const int g = lane >> 2, tg = lane & 3;
#pragma unroll
    for (int mt = 0; mt < 2; ++mt) {
#pragma unroll
        for (int nt = 0; nt < 8; ++nt) {
            const int row0 = m0 + wm + mt * 16 + g;
            const int col = n0 + wn + nt * 8 + tg * 2;
            if (col >= Ng) continue;
            float bc0 = 0.f, bc1 = 0.f;
            if (BIASM == 2) { bc0 = bias[col]; bc1 = bias[col + 1]; }
#pragma unroll
            for (int h = 0; h < 2; ++h) {
                const int row = row0 + h * 8;
                if (row >= Mg) continue;
                float v0 = acc[mt][nt][h * 2], v1 = acc[mt][nt][h * 2 + 1];
                if (BIASM == 1) { float bv = bias[row]; v0 += bv; v1 += bv; }
                if (BIASM == 2) { v0 += bc0; v1 += bc1; }
                const size_t off = (size_t)blockIdx.z * sC + (size_t)row * Ng + col;
                if (OUTM == 0) {
                    float2 v; v.x = v0; v.y = v1;
                    *(float2*)(Cf + off) = v;
                } else if (OUTM == 1) {
                    __nv_bfloat16 h0, l0, h1, l1;
                    split_bf(v0, h0, l0); split_bf(v1, h1, l1);
                    __nv_bfloat162 hp; hp.x = h0; hp.y = h1;
                    __nv_bfloat162 lp; lp.x = l0; lp.y = l1;
                    *(__nv_bfloat162*)((__nv_bfloat16*)ChiV + off) = hp;
                    *(__nv_bfloat162*)((__nv_bfloat16*)CloV + off) = lp;
                } else {
                    __half h0, l0, h1, l1;
                    split_h(v0, h0, l0); split_h(v1, h1, l1);
                    __half2 hp = __halves2half2(h0, h1);
                    __half2 lp = __halves2half2(l0, l1);
                    *(__half2*)((__half*)ChiV + off) = hp;
                    *(__half2*)((__half*)CloV + off) = lp;
                }
            }
        }
    }
}

// ============================================================================
// fp16 2-product engine: C = (Ah+Al)·Bh.  Same geometry as bf16 engine.
// OUTM: 0 = fp32; 1 = bf16 split (with oscale)
// ============================================================================
__device__ __forceinline__ void stage_load_h2(
    uint32_t st_base,
    const __half* Ahi, const __half* Alo, const __half* Bhi,
    int m0, int n0, int Mg, int Ng, int K, int k0, int tid)
{
    const int row = tid >> 1;
    const int cb = (tid & 1) * 4;
    {
        const int gr = m0 + row;
        const uint32_t vsz = (gr < Mg) ? 16u : 0u;
        const int r = (gr < Mg) ? gr : 0;
        const __half* sh = Ahi + (size_t)r * K + k0 + cb * 8;
        const __half* sl = Alo + (size_t)r * K + k0 + cb * 8;
#pragma unroll
        for (int i = 0; i < 4; ++i) {
            uint32_t o = sw_off(row, cb + i);
            cp16(st_base + o,       sh + i * 8, vsz);
            cp16(st_base + A_T + o, sl + i * 8, vsz);
        }
    }
    {
        const int gr = n0 + row;
        const uint32_t vsz = (gr < Ng) ? 16u : 0u;
        const int r = (gr < Ng) ? gr : 0;
        const __half* sh = Bhi + (size_t)r * K + k0 + cb * 8;
#pragma unroll
        for (int i = 0; i < 4; ++i) {
            uint32_t o = sw_off(row, cb + i);
            cp16(st_base + 2 * A_T + o, sh + i * 8, vsz);
        }
    }
}

template <int OUTM>
__global__ void __launch_bounds__(256, 1) mma_gemm_h2(
    const __half* __restrict__ Ahi, const __half* __restrict__ Alo,
    const __half* __restrict__ Bhi,
    float* __restrict__ Cf,
    __nv_bfloat16* __restrict__ Chi, __nv_bfloat16* __restrict__ Clo,
    float oscale,
    int Mg, int Ng, int K,
    long long sA, long long sB, long long sC)
{
    extern __shared__ char smem[];
    const int tid = threadIdx.x;
    const int lane = tid & 31, wid = tid >> 5;
    const int m0 = blockIdx.y * 128, n0 = blockIdx.x * 128;
    Ahi += (size_t)blockIdx.z * sA;  Alo += (size_t)blockIdx.z * sA;
    Bhi += (size_t)blockIdx.z * sB;
    const uint32_t sb = smem_u32(smem);

    const int wm = (wid >> 1) * 32;
    const int wn = (wid & 1) * 64;
    const int gi = lane >> 3, rin = lane & 7;

    float acc[2][8][4];
#pragma unroll
    for (int a = 0; a < 2; ++a)
#pragma unroll
        for (int b = 0; b < 8; ++b)
#pragma unroll
            for (int c = 0; c < 4; ++c) acc[a][b][c] = 0.f;

    const int nkc = K / KC;
    stage_load_h2(sb, Ahi, Alo, Bhi, m0, n0, Mg, Ng, K, 0, tid);
    asm volatile("cp.async.commit_group;" ::: "memory");

    for (int cc = 0; cc < nkc; ++cc) {
        if (cc + 1 < nkc) {
            stage_load_h2(sb + ((cc + 1) & 1) * STG2, Ahi, Alo, Bhi,
                          m0, n0, Mg, Ng, K, (cc + 1) * KC, tid);
            asm volatile("cp.async.commit_group;" ::: "memory");
            asm volatile("cp.async.wait_group 1;" ::: "memory");
        } else {
            asm volatile("cp.async.wait_group 0;" ::: "memory");
        }
        __syncthreads();

        const uint32_t stB = sb + (cc & 1) * STG2;
#pragma unroll
        for (int ks = 0; ks < 4; ++ks) {
            uint32_t Ah[2][4], Al[2][4];
#pragma unroll
            for (int mt = 0; mt < 2; ++mt) {
                const int rowA = wm + mt * 16 + (gi & 1) * 8 + rin;
                const int chA = ks * 2 + (gi >> 1);
                const uint32_t aaddr = stB + sw_off(rowA, chA);
                ldmx4(Ah[mt], aaddr);
                ldmx4(Al[mt], aaddr + A_T);
            }
#pragma unroll
            for (int np = 0; np < 4; ++np) {
                const int rowB = wn + np * 16 + (gi >> 1) * 8 + rin;
                const int chB = ks * 2 + (gi & 1);
                uint32_t Bh[4];
                ldmx4(Bh, stB + 2 * A_T + sw_off(rowB, chB));
#pragma unroll
                for (int mt = 0; mt < 2; ++mt) {
                    mma16816h(acc[mt][np * 2],     Ah[mt], Bh[0], Bh[1]);
                    mma16816h(acc[mt][np * 2],     Al[mt], Bh[0], Bh[1]);
                    mma16816h(acc[mt][np * 2 + 1], Ah[mt], Bh[2], Bh[3]);
                    mma16816h(acc[mt][np * 2 + 1], Al[mt], Bh[2], Bh[3]);
                }
            }
        }
        __syncthreads();
    }

    const int g = lane >> 2, tg = lane & 3;
#pragma unroll
    for (int mt = 0; mt < 2; ++mt) {
#pragma unroll
        for (int nt = 0; nt < 8; ++nt) {
            const int row0 = m0 + wm + mt * 16 + g;
            const int col = n0 + wn + nt * 8 + tg * 2;
            if (col >= Ng) continue;
#pragma unroll
            for (int h = 0; h < 2; ++h) {
                const int row = row0 + h * 8;
                if (row >= Mg) continue;
                float v0 = acc[mt][nt][h * 2] * oscale;
                float v1 = acc[mt][nt][h * 2 + 1] * oscale;
                const size_t off = (size_t)blockIdx.z * sC + (size_t)row * Ng + col;
                if (OUTM == 0) {
                    float2 v; v.x = v0; v.y = v1;
                    *(float2*)(Cf + off) = v;
                } else {
                    __nv_bfloat16 h0, l0, h1, l1;
                    split_bf(v0, h0, l0); split_bf(v1, h1, l1);
                    __nv_bfloat162 hp; hp.x = h0; hp.y = h1;
                    __nv_bfloat162 lp; lp.x = l0; lp.y = l1;
                    *(__nv_bfloat162*)(Chi + off) = hp;
                    *(__nv_bfloat162*)(Clo + off) = lp;
                }
            }
        }
    }
}

// ============================================================================
// x: [B][CD][NN] fp32 -> [B][NN][CD] split bf16 (transpose + split)
// ============================================================================
__global__ __launch_bounds__(256) void split_T_kernel(
    const float* __restrict__ in,
    __nv_bfloat16* __restrict__ ohi, __nv_bfloat16* __restrict__ olo, int CD)
{
    __shared__ float t[32][33];
    const int b = blockIdx.z;
    const int n0 = blockIdx.x * 32, c0 = blockIdx.y * 32;
    const float* src = in + (size_t)b * CD * NN;
    const int tx = threadIdx.x & 31, ty = threadIdx.x >> 5;
#pragma unroll
    for (int r = 0; r < 4; ++r)
        t[ty + r * 8][tx] = src[(size_t)(c0 + ty + r * 8) * NN + n0 + tx];
    __syncthreads();
    __nv_bfloat16* dhi = ohi + (size_t)b * NN * CD;
    __nv_bfloat16* dlo = olo + (size_t)b * NN * CD;
#pragma unroll
    for (int r = 0; r < 4; ++r) {
        float v = t[tx][ty + r * 8];
        __nv_bfloat16 h, l; split_bf(v, h, l);
        size_t o = (size_t)(n0 + ty + r * 8) * CD + c0 + tx;
        dhi[o] = h; dlo[o] = l;
    }
}

// elementwise split (weights)
__global__ __launch_bounds__(256) void split4_kernel(
    const float* __restrict__ in,
    __nv_bfloat16* __restrict__ ohi, __nv_bfloat16* __restrict__ olo, size_t n4)
{
    size_t i = (size_t)blockIdx.x * 256 + threadIdx.x;
    if (i >= n4) return;
    float4 v = ((const float4*)in)[i];
    __nv_bfloat16 h0, l0, h1, l1, h2, l2, h3, l3;
    split_bf(v.x, h0, l0); split_bf(v.y, h1, l1);
    split_bf(v.z, h2, l2); split_bf(v.w, h3, l3);
    __nv_bfloat162 hp0; hp0.x = h0; hp0.y = h1;
    __nv_bfloat162 hp1; hp1.x = h2; hp1.y = h3;
    __nv_bfloat162 lp0; lp0.x = l0; lp0.y = l1;
    __nv_bfloat162 lp1; lp1.x = l2; lp1.y = l3;
    ((__nv_bfloat162*)ohi)[i * 2]     = hp0;
    ((__nv_bfloat162*)ohi)[i * 2 + 1] = hp1;
    ((__nv_bfloat162*)olo)[i * 2]     = lp0;
    ((__nv_bfloat162*)olo)[i * 2 + 1] = lp1;
}

// ============================================================================
// Row softmax over f (fp32 in) -> scaled split fp16 probabilities
// ============================================================================
__global__ __launch_bounds__(256) void softmax_kernel(
    const float* __restrict__ f,
    __half* __restrict__ pf_hi, __half* __restrict__ pf_lo)
{
    __shared__ float4 buf[NN / 4];
    __shared__ float red[8];
    const float* row = f + (size_t)blockIdx.x * NN;
    __half* rh = pf_hi + (size_t)blockIdx.x * NN;
    __half* rl = pf_lo + (size_t)blockIdx.x * NN;
    const int tid = threadIdx.x;

    float mx = -1e30f;
    for (int i = tid; i < NN / 4; i += 256) {
        float4 v = *(const float4*)(row + i * 4);
        buf[i] = v;
        mx = fmaxf(mx, fmaxf(fmaxf(v.x, v.y), fmaxf(v.z, v.w)));
    }
#pragma unroll
    for (int o = 16; o > 0; o >>= 1) mx = fmaxf(mx, __shfl_xor_sync(0xffffffffu, mx, o));
    if ((tid & 31) == 0) red[tid >> 5] = mx;
    __syncthreads();
    if (tid == 0) {
        float v = red[0];
        for (int i = 1; i < 8; ++i) v = fmaxf(v, red[i]);
        red[0] = v;
    }
    __syncthreads();
    mx = red[0];
    __syncthreads();

    float sum = 0.f;
    for (int i = tid; i < NN / 4; i += 256) {
        float4 v = buf[i];
        v.x = __expf(v.x - mx); v.y = __expf(v.y - mx);
        v.z = __expf(v.z - mx); v.w = __expf(v.w - mx);
        buf[i] = v;
        sum += v.x + v.y + v.z + v.w;
    }
#pragma unroll
    for (int o = 16; o > 0; o >>= 1) sum += __shfl_xor_sync(0xffffffffu, sum, o);
    if ((tid & 31) == 0) red[tid >> 5] = sum;
    __syncthreads();
    if (tid == 0) {
        float v = 0.f;
        for (int i = 0; i < 8; ++i) v += red[i];
        red[0] = v;
    }
    __syncthreads();
    const float inv = PF_SCALE / red[0];

    for (int i = tid; i < NN / 4; i += 256) {
        float4 v = buf[i];
        v.x *= inv; v.y *= inv; v.z *= inv; v.w *= inv;
        __half h0, l0, h1, l1, h2, l2, h3, l3;
        split_h(v.x, h0, l0); split_h(v.y, h1, l1);
        split_h(v.z, h2, l2); split_h(v.w, h3, l3);
        ((__half2*)rh)[i * 2]     = __halves2half2(h0, h1);
        ((__half2*)rh)[i * 2 + 1] = __halves2half2(h2, h3);
        ((__half2*)rl)[i * 2]     = __halves2half2(l0, l1);
        ((__half2*)rl)[i * 2 + 1] = __halves2half2(l2, l3);
    }
}

// ============================================================================
// BatchNorm stats + finalize
// ============================================================================
__global__ __launch_bounds__(256) void bnstats_kernel(const float* __restrict__ wy)
{
    const int c = blockIdx.x;
    const int tid = threadIdx.x;
    float s = 0.f, s2 = 0.f;
    for (int b = 0; b < BB; ++b) {
        const float* row = wy + ((size_t)b * CC + c) * NN;
        for (int i = tid; i < NN / 4; i += 256) {
            float4 v = *(const float4*)(row + i * 4);
            s  += v.x + v.y + v.z + v.w;
            s2 += v.x * v.x + v.y * v.y + v.z * v.z + v.w * v.w;
        }
    }
#pragma unroll
    for (int o = 16; o > 0; o >>= 1) {
        s  += __shfl_xor_sync(0xffffffffu, s, o);
        s2 += __shfl_xor_sync(0xffffffffu, s2, o);
    }
    __shared__ float rs[8], rs2[8];
    if ((tid & 31) == 0) { rs[tid >> 5] = s; rs2[tid >> 5] = s2; }
    __syncthreads();
    if (tid == 0) {
        float ts = 0.f, ts2 = 0.f;
        for (int i = 0; i < 8; ++i) { ts += rs[i]; ts2 += rs2[i]; }
        const float cnt = (float)(BB * NN);
        const float mean = ts / cnt;
        const float var = ts2 / cnt - mean * mean;
        s_mean[c] = mean;
        s_rstd[c] = rsqrtf(var + EPSBN);
    }
}

__global__ __launch_bounds__(256) void bn_finalize_kernel(
    const float* __restrict__ wy, const float* __restrict__ x,
    const float* __restrict__ gamma, const float* __restrict__ beta,
    float* __restrict__ out)
{
    const size_t i4 = (size_t)blockIdx.x * 256 + threadIdx.x;
    const size_t total4 = (size_t)BB * CC * NN / 4;
    if (i4 >= total4) return;
    const size_t i = i4 * 4;
    const int c = (int)((i / NN) % CC);
    float4 w  = *(const float4*)(wy + i);
    float4 xv = *(const float4*)(x + i);
    const float m = s_mean[c], r = s_rstd[c];
    const float gm = gamma[c], bt = beta[c];
    float4 o;
    o.x = (w.x - m) * r * gm + bt + xv.x;
    o.y = (w.y - m) * r * gm + bt + xv.y;
    o.z = (w.z - m) * r * gm + bt + xv.z;
    o.w = (w.w - m) * r * gm + bt + xv.w;
    *(float4*)(out + i) = o;
}

// ============================================================================
// Launch
// ============================================================================
extern "C" void kernel_launch(void* const* d_in, const int* in_sizes, int n_in,
                              void* d_out, int out_size)
{
    (void)in_sizes; (void)n_in; (void)out_size;
    const float* x       = (const float*)d_in[0];
    const float* theta_w = (const float*)d_in[1];
    const float* theta_b = (const float*)d_in[2];
    const float* phi_w   = (const float*)d_in[3];
    const float* phi_b   = (const float*)d_in[4];
    const float* g_w     = (const float*)d_in[5];
    const float* g_b     = (const float*)d_in[6];
    const float* w_w     = (const float*)d_in[7];
    const float* w_b     = (const float*)d_in[8];
    const float* gamma   = (const float*)d_in[9];
    const float* beta    = (const float*)d_in[10];
    float* out = (float*)d_out;

    float *p_f, *p_wy;
    __nv_bfloat16 *p_xT_hi, *p_xT_lo, *p_y_hi, *p_y_lo;
    __nv_bfloat16 *p_tw_hi, *p_tw_lo, *p_pw_hi, *p_pw_lo, *p_gw_hi, *p_gw_lo, *p_ww_hi, *p_ww_lo;
    __half *p_thT_hi, *p_thT_lo, *p_phT_hi, *p_phT_lo, *p_gp_hi, *p_gp_lo, *p_pf_hi, *p_pf_lo;
    cudaGetSymbolAddress((void**)&p_f,      s_f);
    cudaGetSymbolAddress((void**)&p_wy,     s_wy);
    cudaGetSymbolAddress((void**)&p_xT_hi,  g_xT_hi);
    cudaGetSymbolAddress((void**)&p_xT_lo,  g_xT_lo);
    cudaGetSymbolAddress((void**)&p_y_hi,   g_y_hi);
    cudaGetSymbolAddress((void**)&p_y_lo,   g_y_lo);
    cudaGetSymbolAddress((void**)&p_tw_hi,  g_tw_hi);
    cudaGetSymbolAddress((void**)&p_tw_lo,  g_tw_lo);
    cudaGetSymbolAddress((void**)&p_pw_hi,  g_pw_hi);
    cudaGetSymbolAddress((void**)&p_pw_lo,  g_pw_lo);
    cudaGetSymbolAddress((void**)&p_gw_hi,  g_gw_hi);
    cudaGetSymbolAddress((void**)&p_gw_lo,  g_gw_lo);
    cudaGetSymbolAddress((void**)&p_ww_hi,  g_ww_hi);
    cudaGetSymbolAddress((void**)&p_ww_lo,  g_ww_lo);
    cudaGetSymbolAddress((void**)&p_thT_hi, g_thT_hi);
    cudaGetSymbolAddress((void**)&p_thT_lo, g_thT_lo);
    cudaGetSymbolAddress((void**)&p_phT_hi, g_phT_hi);
    cudaGetSymbolAddress((void**)&p_phT_lo, g_phT_lo);
    cudaGetSymbolAddress((void**)&p_gp_hi,  g_gp_hi);
    cudaGetSymbolAddress((void**)&p_gp_lo,  g_gp_lo);
    cudaGetSymbolAddress((void**)&p_pf_hi,  g_pf_hi);
    cudaGetSymbolAddress((void**)&p_pf_lo,  g_pf_lo);

    cudaFuncSetAttribute(mma_gemm<0, 1>, cudaFuncAttributeMaxDynamicSharedMemorySize, MMA_SMEM);
    cudaFuncSetAttribute(mma_gemm<2, 1>, cudaFuncAttributeMaxDynamicSharedMemorySize, MMA_SMEM);
    cudaFuncSetAttribute(mma_gemm<2, 2>, cudaFuncAttributeMaxDynamicSharedMemorySize, MMA_SMEM);
    cudaFuncSetAttribute(mma_gemm_h2<0>, cudaFuncAttributeMaxDynamicSharedMemorySize, MMA_SMEM2);
    cudaFuncSetAttribute(mma_gemm_h2<1>, cudaFuncAttributeMaxDynamicSharedMemorySize, MMA_SMEM2);

    const dim3 blk(256);
    const long long sXT = (long long)NN * CC;
    const long long sP  = (long long)CI * NN;   // == NN*CI
    const long long sF  = (long long)NN * NN;

    // 0) operand conversions
    const dim3 gxT(NN / 32, CC / 32, BB);
    split_T_kernel<<<gxT, blk>>>(x, p_xT_hi, p_xT_lo, CC);
    const size_t nw4 = (size_t)CI * CC / 4;
    split4_kernel<<<(unsigned)((nw4 + 255) / 256), blk>>>(theta_w, p_tw_hi, p_tw_lo, nw4);
    split4_kernel<<<(unsigned)((nw4 + 255) / 256), blk>>>(phi_w,   p_pw_hi, p_pw_lo, nw4);
    split4_kernel<<<(unsigned)((nw4 + 255) / 256), blk>>>(g_w,     p_gw_hi, p_gw_lo, nw4);
    split4_kernel<<<(unsigned)((nw4 + 255) / 256), blk>>>(w_w,     p_ww_hi, p_ww_lo, nw4);

    // 1) projections (bf16 3-term engine, fp16-split out, bias fused)
    const dim3 gth(CI / 128, (NN + 127) / 128, BB);   // (2, 25, 8)
    mma_gemm<2, 2><<<gth, blk, MMA_SMEM>>>(p_xT_hi, p_xT_lo, p_tw_hi, p_tw_lo,
        nullptr, p_thT_hi, p_thT_lo, theta_b, NN, CI, CC, sXT, 0, sP);
    mma_gemm<2, 2><<<gth, blk, MMA_SMEM>>>(p_xT_hi, p_xT_lo, p_pw_hi, p_pw_lo,
        nullptr, p_phT_hi, p_phT_lo, phi_b, NN, CI, CC, sXT, 0, sP);
    const dim3 gg((NN + 127) / 128, CI / 128, BB);    // (25, 2, 8)
    mma_gemm<2, 1><<<gg, blk, MMA_SMEM>>>(p_gw_hi, p_gw_lo, p_xT_hi, p_xT_lo,
        nullptr, p_gp_hi, p_gp_lo, g_b, CI, NN, CC, 0, sXT, sP);

    // 2) f[n][m] = (thT_h+thT_l)[n] . phT_h[m]   (fp16 2-product, fp32 out)
    const dim3 gf((NN + 127) / 128, (NN + 127) / 128, BB);   // (25, 25, 8)
    mma_gemm_h2<0><<<gf, blk, MMA_SMEM2>>>(p_thT_hi, p_thT_lo, p_phT_hi,
        p_f, nullptr, nullptr, 1.0f, NN, NN, CI, sP, sP, sF);

    // 3) softmax -> scaled split-fp16 probabilities
    softmax_kernel<<<BB * NN, blk>>>(p_f, p_pf_hi, p_pf_lo);

    // 4) y[n][c] = (Pf_h+Pf_l)[n] . g_h[c]       (fp16 2-product, bf16-split out, /scale)
    const dim3 gy(CI / 128, (NN + 127) / 128, BB);    // (2, 25, 8)
    mma_gemm_h2<1><<<gy, blk, MMA_SMEM2>>>(p_pf_hi, p_pf_lo, p_gp_hi,
        nullptr, p_y_hi, p_y_lo, 1.0f / PF_SCALE, NN, CI, NN, sF, sP, sP);

    // 5) wy[o][n] = w_w[o] . y[n]    (bf16 3-term, fp32 out, row bias)
    const dim3 gw((NN + 127) / 128, CC / 128, BB);    // (25, 4, 8)
    mma_gemm<0, 1><<<gw, blk, MMA_SMEM>>>(p_ww_hi, p_ww_lo, p_y_hi, p_y_lo,
        p_wy, nullptr, nullptr, w_b, CC, NN, CI, 0, sP, (long long)CC * NN);

    // 6) BN stats + finalize with residual
    bnstats_kernel<<<CC, blk>>>(p_wy);
    bn_finalize_kernel<<<(unsigned)((size_t)BB * CC * NN / 4 / 256), blk>>>(p_wy, x, gamma, beta, out);
}

// round 16
// speedup vs baseline: 1.6223x; 1.2859x over previous
#include <cuda_runtime.h>
#include <cuda_bf16.h>
#include <cuda_fp16.h>
#include <cstdint>

#define BB 8
#define CC 512
#define CI 256
#define NN 3136
#define EPSBN 1e-5f
#define PF_SCALE 16384.0f

// ---- scratch (static device globals; no allocations allowed) ----
__device__ __align__(16) float s_f  [BB * NN * NN];            // fp32 scores
__device__ __align__(16) float s_wy [BB * CC * NN];
__device__ float s_mean[CC];
__device__ float s_rstd[CC];

// bf16 split operands (projection inputs + W path)
__device__ __align__(16) __nv_bfloat16 g_xT_hi [BB * NN * CC];
__device__ __align__(16) __nv_bfloat16 g_xT_lo [BB * NN * CC];
__device__ __align__(16) __nv_bfloat16 g_y_hi  [BB * NN * CI];
__device__ __align__(16) __nv_bfloat16 g_y_lo  [BB * NN * CI];
__device__ __align__(16) __nv_bfloat16 g_tw_hi[CI * CC], g_tw_lo[CI * CC];
__device__ __align__(16) __nv_bfloat16 g_pw_hi[CI * CC], g_pw_lo[CI * CC];
__device__ __align__(16) __nv_bfloat16 g_gw_hi[CI * CC], g_gw_lo[CI * CC];
__device__ __align__(16) __nv_bfloat16 g_ww_hi[CC * CI], g_ww_lo[CC * CI];

// fp16 operands (attention path, single precision plane)
__device__ __align__(16) __half g_thT[BB * NN * CI];
__device__ __align__(16) __half g_phT[BB * NN * CI];
__device__ __align__(16) __half g_gp [BB * CI * NN];
__device__ __align__(16) __half g_pf [BB * (size_t)NN * NN];

// ============================================================================
// Warp MMA helpers (sm_80+ ISA only)
// ============================================================================
__device__ __forceinline__ uint32_t smem_u32(const void* p) {
    uint32_t a;
    asm("{ .reg .u64 t; cvta.to.shared.u64 t, %1; cvt.u32.u64 %0, t; }"
        : "=r"(a) : "l"(p));
    return a;
}
__device__ __forceinline__ void ldmx4(uint32_t* r, uint32_t addr) {
    asm volatile("ldmatrix.sync.aligned.m8n8.x4.shared.b16 {%0,%1,%2,%3}, [%4];"
                 : "=r"(r[0]), "=r"(r[1]), "=r"(r[2]), "=r"(r[3]) : "r"(addr));
}
__device__ __forceinline__ void mma16816(float* d, const uint32_t* a,
                                         uint32_t b0, uint32_t b1) {
    asm volatile("mma.sync.aligned.m16n8k16.row.col.f32.bf16.bf16.f32 "
                 "{%0,%1,%2,%3}, {%4,%5,%6,%7}, {%8,%9}, {%0,%1,%2,%3};"
                 : "+f"(d[0]), "+f"(d[1]), "+f"(d[2]), "+f"(d[3])
                 : "r"(a[0]), "r"(a[1]), "r"(a[2]), "r"(a[3]), "r"(b0), "r"(b1));
}
__device__ __forceinline__ void mma16816h(float* d, const uint32_t* a,
                                          uint32_t b0, uint32_t b1) {
    asm volatile("mma.sync.aligned.m16n8k16.row.col.f32.f16.f16.f32 "
                 "{%0,%1,%2,%3}, {%4,%5,%6,%7}, {%8,%9}, {%0,%1,%2,%3};"
                 : "+f"(d[0]), "+f"(d[1]), "+f"(d[2]), "+f"(d[3])
                 : "r"(a[0]), "r"(a[1]), "r"(a[2]), "r"(a[3]), "r"(b0), "r"(b1));
}
__device__ __forceinline__ void cp16(uint32_t saddr, const void* gaddr, uint32_t srcsz) {
    asm volatile("cp.async.cg.shared.global [%0], [%1], 16, %2;"
                 :: "r"(saddr), "l"(gaddr), "r"(srcsz) : "memory");
}
__device__ __forceinline__ void split_bf(float v, __nv_bfloat16& h, __nv_bfloat16& l) {
    h = __float2bfloat16(v);
    l = __float2bfloat16(v - __bfloat162float(h));
}

#define KC 64
#define A_T 16384                    // one 128x64 16-bit tile
#define STG (4 * A_T)                // bf16 engine stage: AH, AL, BH, BL
#define MMA_SMEM (2 * STG)           // 131072
#define STG1 (2 * A_T)               // h1 engine stage: A, B
#define MMA_SMEM1 (2 * STG1)         // 65536

__device__ __forceinline__ uint32_t sw_off(int row, int chunk) {
    return (uint32_t)(row * 128 + ((chunk ^ (row & 7)) << 4));
}

// ============================================================================
// bf16 3-term engine: block 128x128, warps 4(M)x2(N), warp tile 32x64.
// OUTM: 0 = fp32; 1 = bf16 split; 3 = fp16 single.  BIASM: 0/1(row)/2(col)
// ============================================================================
__device__ __forceinline__ void stage_load_bf(
    uint32_t st_base,
    const __nv_bfloat16* Ahi, const __nv_bfloat16* Alo,
    const __nv_bfloat16* Bhi, const __nv_bfloat16* Blo,
    int m0, int n0, int Mg, int Ng, int K, int k0, int tid)
{
    const int row = tid >> 1;
    const int cb = (tid & 1) * 4;
    {
        const int gr = m0 + row;
        const uint32_t vsz = (gr < Mg) ? 16u : 0u;
        const int r = (gr < Mg) ? gr : 0;
        const __nv_bfloat16* sh = Ahi + (size_t)r * K + k0 + cb * 8;
        const __nv_bfloat16* sl = Alo + (size_t)r * K + k0 + cb * 8;
#pragma unroll
        for (int i = 0; i < 4; ++i) {
            uint32_t o = sw_off(row, cb + i);
            cp16(st_base + o,       sh + i * 8, vsz);
            cp16(st_base + A_T + o, sl + i * 8, vsz);
        }
    }
    {
        const int gr = n0 + row;
        const uint32_t vsz = (gr < Ng) ? 16u : 0u;
        const int r = (gr < Ng) ? gr : 0;
        const __nv_bfloat16* sh = Bhi + (size_t)r * K + k0 + cb * 8;
        const __nv_bfloat16* sl = Blo + (size_t)r * K + k0 + cb * 8;
#pragma unroll
        for (int i = 0; i < 4; ++i) {
            uint32_t o = sw_off(row, cb + i);
            cp16(st_base + 2 * A_T + o, sh + i * 8, vsz);
            cp16(st_base + 3 * A_T + o, sl + i * 8, vsz);
        }
    }
}

template <int OUTM, int BIASM>
__global__ void __launch_bounds__(256, 1) mma_gemm(
    const __nv_bfloat16* __restrict__ Ahi, const __nv_bfloat16* __restrict__ Alo,
    const __nv_bfloat16* __restrict__ Bhi, const __nv_bfloat16* __restrict__ Blo,
    float* __restrict__ Cf, void* __restrict__ ChiV, void* __restrict__ CloV,
    const float* __restrict__ bias,
    int Mg, int Ng, int K,
    long long sA, long long sB, long long sC)
{
    extern __shared__ char smem[];
    const int tid = threadIdx.x;
    const int lane = tid & 31, wid = tid >> 5;
    const int m0 = blockIdx.y * 128, n0 = blockIdx.x * 128;
    Ahi += (size_t)blockIdx.z * sA;  Alo += (size_t)blockIdx.z * sA;
    Bhi += (size_t)blockIdx.z * sB;  Blo += (size_t)blockIdx.z * sB;
    const uint32_t sb = smem_u32(smem);

    const int wm = (wid >> 1) * 32;
    const int wn = (wid & 1) * 64;
    const int gi = lane >> 3, rin = lane & 7;

    float acc[2][8][4];
#pragma unroll
    for (int a = 0; a < 2; ++a)
#pragma unroll
        for (int b = 0; b < 8; ++b)
#pragma unroll
            for (int c = 0; c < 4; ++c) acc[a][b][c] = 0.f;

    const int nkc = K / KC;
    stage_load_bf(sb, Ahi, Alo, Bhi, Blo, m0, n0, Mg, Ng, K, 0, tid);
    asm volatile("cp.async.commit_group;" ::: "memory");

    for (int cc = 0; cc < nkc; ++cc) {
        if (cc + 1 < nkc) {
            stage_load_bf(sb + ((cc + 1) & 1) * STG, Ahi, Alo, Bhi, Blo,
                          m0, n0, Mg, Ng, K, (cc + 1) * KC, tid);
            asm volatile("cp.async.commit_group;" ::: "memory");
            asm volatile("cp.async.wait_group 1;" ::: "memory");
        } else {
            asm volatile("cp.async.wait_group 0;" ::: "memory");
        }
        __syncthreads();

        const uint32_t stB = sb + (cc & 1) * STG;
#pragma unroll
        for (int ks = 0; ks < 4; ++ks) {
            uint32_t Ah[2][4], Al[2][4];
#pragma unroll
            for (int mt = 0; mt < 2; ++mt) {
                const int rowA = wm + mt * 16 + (gi & 1) * 8 + rin;
                const int chA = ks * 2 + (gi >> 1);
                const uint32_t aaddr = stB + sw_off(rowA, chA);
                ldmx4(Ah[mt], aaddr);
                ldmx4(Al[mt], aaddr + A_T);
            }
#pragma unroll
            for (int np = 0; np < 4; ++np) {
                const int rowB = wn + np * 16 + (gi >> 1) * 8 + rin;
                const int chB = ks * 2 + (gi & 1);
                const uint32_t baddr = stB + 2 * A_T + sw_off(rowB, chB);
                uint32_t Bh[4], Bl[4];
                ldmx4(Bh, baddr);
                ldmx4(Bl, baddr + A_T);
#pragma unroll
                for (int mt = 0; mt < 2; ++mt) {
                    mma16816(acc[mt][np * 2],     Ah[mt], Bh[0], Bh[1]);
                    mma16816(acc[mt][np * 2],     Al[mt], Bh[0], Bh[1]);
                    mma16816(acc[mt][np * 2],     Ah[mt], Bl[0], Bl[1]);
                    mma16816(acc[mt][np * 2 + 1], Ah[mt], Bh[2], Bh[3]);
                    mma16816(acc[mt][np * 2 + 1], Al[mt], Bh[2], Bh[3]);
                    mma16816(acc[mt][np * 2 + 1], Ah[mt], Bl[2], Bl[3]);
                }
            }
        }
        __syncthreads();
    }

    const int g = lane >> 2, tg = lane & 3;
#pragma unroll
    for (int mt = 0; mt < 2; ++mt) {
#pragma unroll
        for (int nt = 0; nt < 8; ++nt) {
            const int row0 = m0 + wm + mt * 16 + g;
            const int col = n0 + wn + nt * 8 + tg * 2;
            if (col >= Ng) continue;
            float bc0 = 0.f, bc1 = 0.f;
            if (BIASM == 2) { bc0 = bias[col]; bc1 = bias[col + 1]; }
#pragma unroll
            for (int h = 0; h < 2; ++h) {
                const int row = row0 + h * 8;
                if (row >= Mg) continue;
                float v0 = acc[mt][nt][h * 2], v1 = acc[mt][nt][h * 2 + 1];
                if (BIASM == 1) { float bv = bias[row]; v0 += bv; v1 += bv; }
                if (BIASM == 2) { v0 += bc0; v1 += bc1; }
                const size_t off = (size_t)blockIdx.z * sC + (size_t)row * Ng + col;
                if (OUTM == 0) {
                    float2 v; v.x = v0; v.y = v1;
                    *(float2*)(Cf + off) = v;
                } else if (OUTM == 1) {
                    __nv_bfloat16 h0, l0, h1, l1;
                    split_bf(v0, h0, l0); split_bf(v1, h1, l1);
                    __nv_bfloat162 hp; hp.x = h0; hp.y = h1;
                    __nv_bfloat162 lp; lp.x = l0; lp.y = l1;
                    *(__nv_bfloat162*)((__nv_bfloat16*)ChiV + off) = hp;
                    *(__nv_bfloat162*)((__nv_bfloat16*)CloV + off) = lp;
                } else {
                    __half2 hp = __halves2half2(__float2half(v0), __float2half(v1));
                    *(__half2*)((__half*)ChiV + off) = hp;
                }
            }
        }
    }
}

// ============================================================================
// fp16 single-product engine: C = A·B (both fp16). Block 128x128, 32KB/stage.
// OUTM: 0 = fp32; 1 = bf16 split (with oscale)
// ============================================================================
__device__ __forceinline__ void stage_load_h1(
    uint32_t st_base,
    const __half* A, const __half* B,
    int m0, int n0, int Mg, int Ng, int K, int k0, int tid)
{
    const int row = tid >> 1;
    const int cb = (tid & 1) * 4;
    {
        const int gr = m0 + row;
        const uint32_t vsz = (gr < Mg) ? 16u : 0u;
        const int r = (gr < Mg) ? gr : 0;
        const __half* s = A + (size_t)r * K + k0 + cb * 8;
#pragma unroll
        for (int i = 0; i < 4; ++i)
            cp16(st_base + sw_off(row, cb + i), s + i * 8, vsz);
    }
    {
        const int gr = n0 + row;
        const uint32_t vsz = (gr < Ng) ? 16u : 0u;
        const int r = (gr < Ng) ? gr : 0;
        const __half* s = B + (size_t)r * K + k0 + cb * 8;
#pragma unroll
        for (int i = 0; i < 4; ++i)
            cp16(st_base + A_T + sw_off(row, cb + i), s + i * 8, vsz);
    }
}

template <int OUTM>
__global__ void __launch_bounds__(256, 1) mma_gemm_h1(
    const __half* __restrict__ A, const __half* __restrict__ B,
    float* __restrict__ Cf,
    __nv_bfloat16* __restrict__ Chi, __nv_bfloat16* __restrict__ Clo,
    float oscale,
    int Mg, int Ng, int K,
    long long sA, long long sB, long long sC)
{
    extern __shared__ char smem[];
    const int tid = threadIdx.x;
    const int lane = tid & 31, wid = tid >> 5;
    const int m0 = blockIdx.y * 128, n0 = blockIdx.x * 128;
    A += (size_t)blockIdx.z * sA;
    B += (size_t)blockIdx.z * sB;
    const uint32_t sb = smem_u32(smem);

    const int wm = (wid >> 1) * 32;
    const int wn = (wid & 1) * 64;
    const int gi = lane >> 3, rin = lane & 7;

    float acc[2][8][4];
#pragma unroll
    for (int a = 0; a < 2; ++a)
#pragma unroll
        for (int b = 0; b < 8; ++b)
#pragma unroll
            for (int c = 0; c < 4; ++c) acc[a][b][c] = 0.f;

    const int nkc = K / KC;
    stage_load_h1(sb, A, B, m0, n0, Mg, Ng, K, 0, tid);
    asm volatile("cp.async.commit_group;" ::: "memory");

    for (int cc = 0; cc < nkc; ++cc) {
        if (cc + 1 < nkc) {
            stage_load_h1(sb + ((cc + 1) & 1) * STG1, A, B,
                          m0, n0, Mg, Ng, K, (cc + 1) * KC, tid);
            asm volatile("cp.async.commit_group;" ::: "memory");
            asm volatile("cp.async.wait_group 1;" ::: "memory");
        } else {
            asm volatile("cp.async.wait_group 0;" ::: "memory");
        }
        __syncthreads();

        const uint32_t stB = sb + (cc & 1) * STG1;
#pragma unroll
        for (int ks = 0; ks < 4; ++ks) {
            uint32_t Ar[2][4];
#pragma unroll
            for (int mt = 0; mt < 2; ++mt) {
                const int rowA = wm + mt * 16 + (gi & 1) * 8 + rin;
                const int chA = ks * 2 + (gi >> 1);
                ldmx4(Ar[mt], stB + sw_off(rowA, chA));
            }
#pragma unroll
            for (int np = 0; np < 4; ++np) {
                const int rowB = wn + np * 16 + (gi >> 1) * 8 + rin;
                const int chB = ks * 2 + (gi & 1);
                uint32_t Br[4];
                ldmx4(Br, stB + A_T + sw_off(rowB, chB));
#pragma unroll
                for (int mt = 0; mt < 2; ++mt) {
                    mma16816h(acc[mt][np * 2],     Ar[mt], Br[0], Br[1]);
                    mma16816h(acc[mt][np * 2 + 1], Ar[mt], Br[2], Br[3]);
                }
            }
        }
        __syncthreads();
    }

    const int g = lane >> 2, tg = lane & 3;
#pragma unroll
    for (int mt = 0; mt < 2; ++mt) {
#pragma unroll
        for (int nt = 0; nt < 8; ++nt) {
            const int row0 = m0 + wm + mt * 16 + g;
            const int col = n0 + wn + nt * 8 + tg * 2;
            if (col >= Ng) continue;
#pragma unroll
            for (int h = 0; h < 2; ++h) {
                const int row = row0 + h * 8;
                if (row >= Mg) continue;
                float v0 = acc[mt][nt][h * 2] * oscale;
                float v1 = acc[mt][nt][h * 2 + 1] * oscale;
                const size_t off = (size_t)blockIdx.z * sC + (size_t)row * Ng + col;
                if (OUTM == 0) {
                    float2 v; v.x = v0; v.y = v1;
                    *(float2*)(Cf + off) = v;
                } else {
                    __nv_bfloat16 h0, l0, h1, l1;
                    split_bf(v0, h0, l0); split_bf(v1, h1, l1);
                    __nv_bfloat162 hp; hp.x = h0; hp.y = h1;
                    __nv_bfloat162 lp; lp.x = l0; lp.y = l1;
                    *(__nv_bfloat162*)(Chi + off) = hp;
                    *(__nv_bfloat162*)(Clo + off) = lp;
                }
            }
        }
    }
}

// ============================================================================
// x: [B][CD][NN] fp32 -> [B][NN][CD] split bf16 (transpose + split)
// ============================================================================
__global__ __launch_bounds__(256) void split_T_kernel(
    const float* __restrict__ in,
    __nv_bfloat16* __restrict__ ohi, __nv_bfloat16* __restrict__ olo, int CD)
{
    __shared__ float t[32][33];
    const int b = blockIdx.z;
    const int n0 = blockIdx.x * 32, c0 = blockIdx.y * 32;
    const float* src = in + (size_t)b * CD * NN;
    const int tx = threadIdx.x & 31, ty = threadIdx.x >> 5;
#pragma unroll
    for (int r = 0; r < 4; ++r)
        t[ty + r * 8][tx] = src[(size_t)(c0 + ty + r * 8) * NN + n0 + tx];
    __syncthreads();
    __nv_bfloat16* dhi = ohi + (size_t)b * NN * CD;
    __nv_bfloat16* dlo = olo + (size_t)b * NN * CD;
#pragma unroll
    for (int r = 0; r < 4; ++r) {
        float v = t[tx][ty + r * 8];
        __nv_bfloat16 h, l; split_bf(v, h, l);
        size_t o = (size_t)(n0 + ty + r * 8) * CD + c0 + tx;
        dhi[o] = h; dlo[o] = l;
    }
}

// elementwise split (weights)
__global__ __launch_bounds__(256) void split4_kernel(
    const float* __restrict__ in,
    __nv_bfloat16* __restrict__ ohi, __nv_bfloat16* __restrict__ olo, size_t n4)
{
    size_t i = (size_t)blockIdx.x * 256 + threadIdx.x;
    if (i >= n4) return;
    float4 v = ((const float4*)in)[i];
    __nv_bfloat16 h0, l0, h1, l1, h2, l2, h3, l3;
    split_bf(v.x, h0, l0); split_bf(v.y, h1, l1);
    split_bf(v.z, h2, l2); split_bf(v.w, h3, l3);
    __nv_bfloat162 hp0; hp0.x = h0; hp0.y = h1;
    __nv_bfloat162 hp1; hp1.x = h2; hp1.y = h3;
    __nv_bfloat162 lp0; lp0.x = l0; lp0.y = l1;
    __nv_bfloat162 lp1; lp1.x = l2; lp1.y = l3;
    ((__nv_bfloat162*)ohi)[i * 2]     = hp0;
    ((__nv_bfloat162*)ohi)[i * 2 + 1] = hp1;
    ((__nv_bfloat162*)olo)[i * 2]     = lp0;
    ((__nv_bfloat162*)olo)[i * 2 + 1] = lp1;
}

// ============================================================================
// Row softmax over f (fp32 in) -> scaled fp16 probabilities
// ============================================================================
__global__ __launch_bounds__(256) void softmax_kernel(
    const float* __restrict__ f, __half* __restrict__ pf)
{
    __shared__ float4 buf[NN / 4];
    __shared__ float red[8];
    const float* row = f + (size_t)blockIdx.x * NN;
    __half* rp = pf + (size_t)blockIdx.x * NN;
    const int tid = threadIdx.x;

    float mx = -1e30f;
    for (int i = tid; i < NN / 4; i += 256) {
        float4 v = *(const float4*)(row + i * 4);
        buf[i] = v;
        mx = fmaxf(mx, fmaxf(fmaxf(v.x, v.y), fmaxf(v.z, v.w)));
    }
#pragma unroll
    for (int o = 16; o > 0; o >>= 1) mx = fmaxf(mx, __shfl_xor_sync(0xffffffffu, mx, o));
    if ((tid & 31) == 0) red[tid >> 5] = mx;
    __syncthreads();
    if (tid == 0) {
        float v = red[0];
        for (int i = 1; i < 8; ++i) v = fmaxf(v, red[i]);
        red[0] = v;
    }
    __syncthreads();
    mx = red[0];
    __syncthreads();

    float sum = 0.f;
    for (int i = tid; i < NN / 4; i += 256) {
        float4 v = buf[i];
        v.x = __expf(v.x - mx); v.y = __expf(v.y - mx);
        v.z = __expf(v.z - mx); v.w = __expf(v.w - mx);
        buf[i] = v;
        sum += v.x + v.y + v.z + v.w;
    }
#pragma unroll
    for (int o = 16; o > 0; o >>= 1) sum += __shfl_xor_sync(0xffffffffu, sum, o);
    if ((tid & 31) == 0) red[tid >> 5] = sum;
    __syncthreads();
    if (tid == 0) {
        float v = 0.f;
        for (int i = 0; i < 8; ++i) v += red[i];
        red[0] = v;
    }
    __syncthreads();
    const float inv = PF_SCALE / red[0];

    for (int i = tid; i < NN / 4; i += 256) {
        float4 v = buf[i];
        ((__half2*)rp)[i * 2] =
            __halves2half2(__float2half(v.x * inv), __float2half(v.y * inv));
        ((__half2*)rp)[i * 2 + 1] =
            __halves2half2(__float2half(v.z * inv), __float2half(v.w * inv));
    }
}

// ============================================================================
// BatchNorm stats + finalize
// ============================================================================
__global__ __launch_bounds__(256) void bnstats_kernel(const float* __restrict__ wy)
{
    const int c = blockIdx.x;
    const int tid = threadIdx.x;
    float s = 0.f, s2 = 0.f;
    for (int b = 0; b < BB; ++b) {
        const float* row = wy + ((size_t)b * CC + c) * NN;
        for (int i = tid; i < NN / 4; i += 256) {
            float4 v = *(const float4*)(row + i * 4);
            s  += v.x + v.y + v.z + v.w;
            s2 += v.x * v.x + v.y * v.y + v.z * v.z + v.w * v.w;
        }
    }
#pragma unroll
    for (int o = 16; o > 0; o >>= 1) {
        s  += __shfl_xor_sync(0xffffffffu, s, o);
        s2 += __shfl_xor_sync(0xffffffffu, s2, o);
    }
    __shared__ float rs[8], rs2[8];
    if ((tid & 31) == 0) { rs[tid >> 5] = s; rs2[tid >> 5] = s2; }
    __syncthreads();
    if (tid == 0) {
        float ts = 0.f, ts2 = 0.f;
        for (int i = 0; i < 8; ++i) { ts += rs[i]; ts2 += rs2[i]; }
        const float cnt = (float)(BB * NN);
        const float mean = ts / cnt;
        const float var = ts2 / cnt - mean * mean;
        s_mean[c] = mean;
        s_rstd[c] = rsqrtf(var + EPSBN);
    }
}

__global__ __launch_bounds__(256) void bn_finalize_kernel(
    const float* __restrict__ wy, const float* __restrict__ x,
    const float* __restrict__ gamma, const float* __restrict__ beta,
    float* __restrict__ out)
{
    const size_t i4 = (size_t)blockIdx.x * 256 + threadIdx.x;
    const size_t total4 = (size_t)BB * CC * NN / 4;
    if (i4 >= total4) return;
    const size_t i = i4 * 4;
    const int c = (int)((i / NN) % CC);
    float4 w  = *(const float4*)(wy + i);
    float4 xv = *(const float4*)(x + i);
    const float m = s_mean[c], r = s_rstd[c];
    const float gm = gamma[c], bt = beta[c];
    float4 o;
    o.x = (w.x - m) * r * gm + bt + xv.x;
    o.y = (w.y - m) * r * gm + bt + xv.y;
    o.z = (w.z - m) * r * gm + bt + xv.z;
    o.w = (w.w - m) * r * gm + bt + xv.w;
    *(float4*)(out + i) = o;
}

// ============================================================================
// Launch
// ============================================================================
extern "C" void kernel_launch(void* const* d_in, const int* in_sizes, int n_in,
                              void* d_out, int out_size)
{
    (void)in_sizes; (void)n_in; (void)out_size;
    const float* x       = (const float*)d_in[0];
    const float* theta_w = (const float*)d_in[1];
    const float* theta_b = (const float*)d_in[2];
    const float* phi_w   = (const float*)d_in[3];
    const float* phi_b   = (const float*)d_in[4];
    const float* g_w     = (const float*)d_in[5];
    const float* g_b     = (const float*)d_in[6];
    const float* w_w     = (const float*)d_in[7];
    const float* w_b     = (const float*)d_in[8];
    const float* gamma   = (const float*)d_in[9];
    const float* beta    = (const float*)d_in[10];
    float* out = (float*)d_out;

    float *p_f, *p_wy;
    __nv_bfloat16 *p_xT_hi, *p_xT_lo, *p_y_hi, *p_y_lo;
    __nv_bfloat16 *p_tw_hi, *p_tw_lo, *p_pw_hi, *p_pw_lo, *p_gw_hi, *p_gw_lo, *p_ww_hi, *p_ww_lo;
    __half *p_thT, *p_phT, *p_gp, *p_pf;
    cudaGetSymbolAddress((void**)&p_f,      s_f);
    cudaGetSymbolAddress((void**)&p_wy,     s_wy);
    cudaGetSymbolAddress((void**)&p_xT_hi,  g_xT_hi);
    cudaGetSymbolAddress((void**)&p_xT_lo,  g_xT_lo);
    cudaGetSymbolAddress((void**)&p_y_hi,   g_y_hi);
    cudaGetSymbolAddress((void**)&p_y_lo,   g_y_lo);
    cudaGetSymbolAddress((void**)&p_tw_hi,  g_tw_hi);
    cudaGetSymbolAddress((void**)&p_tw_lo,  g_tw_lo);
    cudaGetSymbolAddress((void**)&p_pw_hi,  g_pw_hi);
    cudaGetSymbolAddress((void**)&p_pw_lo,  g_pw_lo);
    cudaGetSymbolAddress((void**)&p_gw_hi,  g_gw_hi);
    cudaGetSymbolAddress((void**)&p_gw_lo,  g_gw_lo);
    cudaGetSymbolAddress((void**)&p_ww_hi,  g_ww_hi);
    cudaGetSymbolAddress((void**)&p_ww_lo,  g_ww_lo);
    cudaGetSymbolAddress((void**)&p_thT,    g_thT);
    cudaGetSymbolAddress((void**)&p_phT,    g_phT);
    cudaGetSymbolAddress((void**)&p_gp,     g_gp);
    cudaGetSymbolAddress((void**)&p_pf,     g_pf);

    cudaFuncSetAttribute(mma_gemm<0, 1>, cudaFuncAttributeMaxDynamicSharedMemorySize, MMA_SMEM);
    cudaFuncSetAttribute(mma_gemm<3, 1>, cudaFuncAttributeMaxDynamicSharedMemorySize, MMA_SMEM);
    cudaFuncSetAttribute(mma_gemm<3, 2>, cudaFuncAttributeMaxDynamicSharedMemorySize, MMA_SMEM);
    cudaFuncSetAttribute(mma_gemm_h1<0>, cudaFuncAttributeMaxDynamicSharedMemorySize, MMA_SMEM1);
    cudaFuncSetAttribute(mma_gemm_h1<1>, cudaFuncAttributeMaxDynamicSharedMemorySize, MMA_SMEM1);

    const dim3 blk(256);
    const long long sXT = (long long)NN * CC;
    const long long sP  = (long long)CI * NN;   // == NN*CI
    const long long sF  = (long long)NN * NN;

    // 0) operand conversions
    const dim3 gxT(NN / 32, CC / 32, BB);
    split_T_kernel<<<gxT, blk>>>(x, p_xT_hi, p_xT_lo, CC);
    const size_t nw4 = (size_t)CI * CC / 4;
    split4_kernel<<<(unsigned)((nw4 + 255) / 256), blk>>>(theta_w, p_tw_hi, p_tw_lo, nw4);
    split4_kernel<<<(unsigned)((nw4 + 255) / 256), blk>>>(phi_w,   p_pw_hi, p_pw_lo, nw4);
    split4_kernel<<<(unsigned)((nw4 + 255) / 256), blk>>>(g_w,     p_gw_hi, p_gw_lo, nw4);
    split4_kernel<<<(unsigned)((nw4 + 255) / 256), blk>>>(w_w,     p_ww_hi, p_ww_lo, nw4);

    // 1) projections (bf16 3-term engine, fp16 out, bias fused)
    const dim3 gth(CI / 128, (NN + 127) / 128, BB);   // (2, 25, 8)
    mma_gemm<3, 2><<<gth, blk, MMA_SMEM>>>(p_xT_hi, p_xT_lo, p_tw_hi, p_tw_lo,
        nullptr, p_thT, nullptr, theta_b, NN, CI, CC, sXT, 0, sP);
    mma_gemm<3, 2><<<gth, blk, MMA_SMEM>>>(p_xT_hi, p_xT_lo, p_pw_hi, p_pw_lo,
        nullptr, p_phT, nullptr, phi_b, NN, CI, CC, sXT, 0, sP);
    const dim3 gg((NN + 127) / 128, CI / 128, BB);    // (25, 2, 8)
    mma_gemm<3, 1><<<gg, blk, MMA_SMEM>>>(p_gw_hi, p_gw_lo, p_xT_hi, p_xT_lo,
        nullptr, p_gp, nullptr, g_b, CI, NN, CC, 0, sXT, sP);

    // 2) f[n][m] = thT[n] . phT[m]   (fp16 single product, fp32 out)
    const dim3 gf((NN + 127) / 128, (NN + 127) / 128, BB);   // (25, 25, 8)
    mma_gemm_h1<0><<<gf, blk, MMA_SMEM1>>>(p_thT, p_phT,
        p_f, nullptr, nullptr, 1.0f, NN, NN, CI, sP, sP, sF);

    // 3) softmax -> scaled fp16 probabilities
    softmax_kernel<<<BB * NN, blk>>>(p_f, p_pf);

    // 4) y[n][c] = Pf[n] . g[c]      (fp16 single product, bf16-split out, /scale)
    const dim3 gy(CI / 128, (NN + 127) / 128, BB);    // (2, 25, 8)
    mma_gemm_h1<1><<<gy, blk, MMA_SMEM1>>>(p_pf, p_gp,
        nullptr, p_y_hi, p_y_lo, 1.0f / PF_SCALE, NN, CI, NN, sF, sP, sP);

    // 5) wy[o][n] = w_w[o] . y[n]    (bf16 3-term, fp32 out, row bias)
    const dim3 gw((NN + 127) / 128, CC / 128, BB);    // (25, 4, 8)
    mma_gemm<0, 1><<<gw, blk, MMA_SMEM>>>(p_ww_hi, p_ww_lo, p_y_hi, p_y_lo,
        p_wy, nullptr, nullptr, w_b, CC, NN, CI, 0, sP, (long long)CC * NN);

    // 6) BN stats + finalize with residual
    bnstats_kernel<<<CC, blk>>>(p_wy);
    bn_finalize_kernel<<<(unsigned)((size_t)BB * CC * NN / 4 / 256), blk>>>(p_wy, x, gamma, beta, out);
}

// round 17
// speedup vs baseline: 2.0168x; 1.2432x over previous
#include <cuda_runtime.h>
#include <cuda_bf16.h>
#include <cuda_fp16.h>
#include <cstdint>

#define BB 8
#define CC 512
#define CI 256
#define NN 3136
#define EPSBN 1e-5f
#define PF_SCALE 16384.0f

// ---- scratch (static device globals; no allocations allowed) ----
__device__ __align__(16) float s_wy [BB * CC * NN];
__device__ float s_mean[CC];
__device__ float s_rstd[CC];

// fp16 operands
__device__ __align__(16) __half g_xT [BB * NN * CC];           // x^T [B][N][C]
__device__ __align__(16) __half g_thT[BB * NN * CI];
__device__ __align__(16) __half g_phT[BB * NN * CI];
__device__ __align__(16) __half g_gp [BB * CI * NN];
__device__ __align__(16) __half g_y  [BB * NN * CI];
__device__ __align__(16) __half g_f  [BB * (size_t)NN * NN];   // fp16 scores
__device__ __align__(16) __half g_pf [BB * (size_t)NN * NN];
__device__ __align__(16) __half g_tw[CI * CC];
__device__ __align__(16) __half g_pw[CI * CC];
__device__ __align__(16) __half g_gw[CI * CC];
__device__ __align__(16) __half g_ww[CC * CI];

// ============================================================================
// Warp MMA helpers (sm_80+ ISA only)
// ============================================================================
__device__ __forceinline__ uint32_t smem_u32(const void* p) {
    uint32_t a;
    asm("{ .reg .u64 t; cvta.to.shared.u64 t, %1; cvt.u32.u64 %0, t; }"
        : "=r"(a) : "l"(p));
    return a;
}
__device__ __forceinline__ void ldmx4(uint32_t* r, uint32_t addr) {
    asm volatile("ldmatrix.sync.aligned.m8n8.x4.shared.b16 {%0,%1,%2,%3}, [%4];"
                 : "=r"(r[0]), "=r"(r[1]), "=r"(r[2]), "=r"(r[3]) : "r"(addr));
}
__device__ __forceinline__ void mma16816h(float* d, const uint32_t* a,
                                          uint32_t b0, uint32_t b1) {
    asm volatile("mma.sync.aligned.m16n8k16.row.col.f32.f16.f16.f32 "
                 "{%0,%1,%2,%3}, {%4,%5,%6,%7}, {%8,%9}, {%0,%1,%2,%3};"
                 : "+f"(d[0]), "+f"(d[1]), "+f"(d[2]), "+f"(d[3])
                 : "r"(a[0]), "r"(a[1]), "r"(a[2]), "r"(a[3]), "r"(b0), "r"(b1));
}
__device__ __forceinline__ void cp16(uint32_t saddr, const void* gaddr, uint32_t srcsz) {
    asm volatile("cp.async.cg.shared.global [%0], [%1], 16, %2;"
                 :: "r"(saddr), "l"(gaddr), "r"(srcsz) : "memory");
}

#define KC 64
#define A_T 16384                    // one 128x64 fp16 tile
#define STG1 (2 * A_T)               // stage: A, B
#define MMA_SMEM1 (2 * STG1)         // 65536

__device__ __forceinline__ uint32_t sw_off(int row, int chunk) {
    return (uint32_t)(row * 128 + ((chunk ^ (row & 7)) << 4));
}

// ============================================================================
// fp16 single-product engine: C = A·B^T. Block 128x128, warps 4(M)x2(N),
// warp tile 32x64, Kc=64, 2-stage cp.async.
// OUTM: 0 = fp32 out; 1 = fp16 out.  BIASM: 0 none / 1 bias[m] / 2 bias[n]
// ============================================================================
__device__ __forceinline__ void stage_load_h1(
    uint32_t st_base,
    const __half* A, const __half* B,
    int m0, int n0, int Mg, int Ng, int K, int k0, int tid)
{
    const int row = tid >> 1;
    const int cb = (tid & 1) * 4;
    {
        const int gr = m0 + row;
        const uint32_t vsz = (gr < Mg) ? 16u : 0u;
        const int r = (gr < Mg) ? gr : 0;
        const __half* s = A + (size_t)r * K + k0 + cb * 8;
#pragma unroll
        for (int i = 0; i < 4; ++i)
            cp16(st_base + sw_off(row, cb + i), s + i * 8, vsz);
    }
    {
        const int gr = n0 + row;
        const uint32_t vsz = (gr < Ng) ? 16u : 0u;
        const int r = (gr < Ng) ? gr : 0;
        const __half* s = B + (size_t)r * K + k0 + cb * 8;
#pragma unroll
        for (int i = 0; i < 4; ++i)
            cp16(st_base + A_T + sw_off(row, cb + i), s + i * 8, vsz);
    }
}

template <int OUTM, int BIASM>
__global__ void __launch_bounds__(256, 1) mma_h1(
    const __half* __restrict__ A, const __half* __restrict__ B,
    float* __restrict__ Cf, __half* __restrict__ Ch,
    const float* __restrict__ bias, float oscale,
    int Mg, int Ng, int K,
    long long sA, long long sB, long long sC)
{
    extern __shared__ char smem[];
    const int tid = threadIdx.x;
    const int lane = tid & 31, wid = tid >> 5;
    const int m0 = blockIdx.y * 128, n0 = blockIdx.x * 128;
    A += (size_t)blockIdx.z * sA;
    B += (size_t)blockIdx.z * sB;
    const uint32_t sb = smem_u32(smem);

    const int wm = (wid >> 1) * 32;
    const int wn = (wid & 1) * 64;
    const int gi = lane >> 3, rin = lane & 7;

    float acc[2][8][4];
#pragma unroll
    for (int a = 0; a < 2; ++a)
#pragma unroll
        for (int b = 0; b < 8; ++b)
#pragma unroll
            for (int c = 0; c < 4; ++c) acc[a][b][c] = 0.f;

    const int nkc = K / KC;
    stage_load_h1(sb, A, B, m0, n0, Mg, Ng, K, 0, tid);
    asm volatile("cp.async.commit_group;" ::: "memory");

    for (int cc = 0; cc < nkc; ++cc) {
        if (cc + 1 < nkc) {
            stage_load_h1(sb + ((cc + 1) & 1) * STG1, A, B,
                          m0, n0, Mg, Ng, K, (cc + 1) * KC, tid);
            asm volatile("cp.async.commit_group;" ::: "memory");
            asm volatile("cp.async.wait_group 1;" ::: "memory");
        } else {
            asm volatile("cp.async.wait_group 0;" ::: "memory");
        }
        __syncthreads();

        const uint32_t stB = sb + (cc & 1) * STG1;
#pragma unroll
        for (int ks = 0; ks < 4; ++ks) {
            uint32_t Ar[2][4];
#pragma unroll
            for (int mt = 0; mt < 2; ++mt) {
                const int rowA = wm + mt * 16 + (gi & 1) * 8 + rin;
                const int chA = ks * 2 + (gi >> 1);
                ldmx4(Ar[mt], stB + sw_off(rowA, chA));
            }
#pragma unroll
            for (int np = 0; np < 4; ++np) {
                const int rowB = wn + np * 16 + (gi >> 1) * 8 + rin;
                const int chB = ks * 2 + (gi & 1);
                uint32_t Br[4];
                ldmx4(Br, stB + A_T + sw_off(rowB, chB));
#pragma unroll
                for (int mt = 0; mt < 2; ++mt) {
                    mma16816h(acc[mt][np * 2],     Ar[mt], Br[0], Br[1]);
                    mma16816h(acc[mt][np * 2 + 1], Ar[mt], Br[2], Br[3]);
                }
            }
        }
        __syncthreads();
    }

    const int g = lane >> 2, tg = lane & 3;
#pragma unroll
    for (int mt = 0; mt < 2; ++mt) {
#pragma unroll
        for (int nt = 0; nt < 8; ++nt) {
            const int row0 = m0 + wm + mt * 16 + g;
            const int col = n0 + wn + nt * 8 + tg * 2;
            if (col >= Ng) continue;
            float bc0 = 0.f, bc1 = 0.f;
            if (BIASM == 2) { bc0 = bias[col]; bc1 = bias[col + 1]; }
#pragma unroll
            for (int h = 0; h < 2; ++h) {
                const int row = row0 + h * 8;
                if (row >= Mg) continue;
                float v0 = acc[mt][nt][h * 2] * oscale;
                float v1 = acc[mt][nt][h * 2 + 1] * oscale;
                if (BIASM == 1) { float bv = bias[row]; v0 += bv; v1 += bv; }
                if (BIASM == 2) { v0 += bc0; v1 += bc1; }
                const size_t off = (size_t)blockIdx.z * sC + (size_t)row * Ng + col;
                if (OUTM == 0) {
                    float2 v; v.x = v0; v.y = v1;
                    *(float2*)(Cf + off) = v;
                } else {
                    *(__half2*)(Ch + off) =
                        __halves2half2(__float2half(v0), __float2half(v1));
                }
            }
        }
    }
}

// ============================================================================
// x: [B][CD][NN] fp32 -> [B][NN][CD] fp16 (transpose + convert)
// ============================================================================
__global__ __launch_bounds__(256) void transpose16_kernel(
    const float* __restrict__ in, __half* __restrict__ o, int CD)
{
    __shared__ float t[32][33];
    const int b = blockIdx.z;
    const int n0 = blockIdx.x * 32, c0 = blockIdx.y * 32;
    const float* src = in + (size_t)b * CD * NN;
    const int tx = threadIdx.x & 31, ty = threadIdx.x >> 5;
#pragma unroll
    for (int r = 0; r < 4; ++r)
        t[ty + r * 8][tx] = src[(size_t)(c0 + ty + r * 8) * NN + n0 + tx];
    __syncthreads();
    __half* dst = o + (size_t)b * NN * CD;
#pragma unroll
    for (int r = 0; r < 4; ++r) {
        float v = t[tx][ty + r * 8];
        dst[(size_t)(n0 + ty + r * 8) * CD + c0 + tx] = __float2half(v);
    }
}

// elementwise fp32 -> fp16 (weights)
__global__ __launch_bounds__(256) void conv16_kernel(
    const float* __restrict__ in, __half* __restrict__ o, size_t n4)
{
    size_t i = (size_t)blockIdx.x * 256 + threadIdx.x;
    if (i >= n4) return;
    float4 v = ((const float4*)in)[i];
    ((__half2*)o)[i * 2]     = __halves2half2(__float2half(v.x), __float2half(v.y));
    ((__half2*)o)[i * 2 + 1] = __halves2half2(__float2half(v.z), __float2half(v.w));
}

// ============================================================================
// Row softmax over f (fp16 in) -> scaled fp16 probabilities
// ============================================================================
__global__ __launch_bounds__(256) void softmax_kernel(
    const __half* __restrict__ f, __half* __restrict__ pf)
{
    __shared__ float buf[NN];
    __shared__ float red[8];
    const __half* row = f + (size_t)blockIdx.x * NN;
    __half* rp = pf + (size_t)blockIdx.x * NN;
    const int tid = threadIdx.x;

    float mx = -1e30f;
    for (int i = tid; i < NN / 8; i += 256) {
        uint4 raw = *(const uint4*)(row + i * 8);
        __half2 h0 = *(__half2*)&raw.x, h1 = *(__half2*)&raw.y;
        __half2 h2 = *(__half2*)&raw.z, h3 = *(__half2*)&raw.w;
        float2 f0 = __half22float2(h0), f1 = __half22float2(h1);
        float2 f2 = __half22float2(h2), f3 = __half22float2(h3);
        buf[i * 8 + 0] = f0.x; buf[i * 8 + 1] = f0.y;
        buf[i * 8 + 2] = f1.x; buf[i * 8 + 3] = f1.y;
        buf[i * 8 + 4] = f2.x; buf[i * 8 + 5] = f2.y;
        buf[i * 8 + 6] = f3.x; buf[i * 8 + 7] = f3.y;
        mx = fmaxf(mx, fmaxf(fmaxf(f0.x, f0.y), fmaxf(f1.x, f1.y)));
        mx = fmaxf(mx, fmaxf(fmaxf(f2.x, f2.y), fmaxf(f3.x, f3.y)));
    }
#pragma unroll
    for (int o = 16; o > 0; o >>= 1) mx = fmaxf(mx, __shfl_xor_sync(0xffffffffu, mx, o));
    if ((tid & 31) == 0) red[tid >> 5] = mx;
    __syncthreads();
    if (tid == 0) {
        float v = red[0];
        for (int i = 1; i < 8; ++i) v = fmaxf(v, red[i]);
        red[0] = v;
    }
    __syncthreads();
    mx = red[0];
    __syncthreads();

    float sum = 0.f;
    for (int i = tid; i < NN; i += 256) {
        float e = __expf(buf[i] - mx);
        buf[i] = e;
        sum += e;
    }
#pragma unroll
    for (int o = 16; o > 0; o >>= 1) sum += __shfl_xor_sync(0xffffffffu, sum, o);
    if ((tid & 31) == 0) red[tid >> 5] = sum;
    __syncthreads();
    if (tid == 0) {
        float v = 0.f;
        for (int i = 0; i < 8; ++i) v += red[i];
        red[0] = v;
    }
    __syncthreads();
    const float inv = PF_SCALE / red[0];

    for (int i = tid; i < NN / 2; i += 256) {
        ((__half2*)rp)[i] = __halves2half2(
            __float2half(buf[i * 2] * inv), __float2half(buf[i * 2 + 1] * inv));
    }
}

// ============================================================================
// BatchNorm stats + finalize
// ============================================================================
__global__ __launch_bounds__(256) void bnstats_kernel(const float* __restrict__ wy)
{
    const int c = blockIdx.x;
    const int tid = threadIdx.x;
    float s = 0.f, s2 = 0.f;
    for (int b = 0; b < BB; ++b) {
        const float* row = wy + ((size_t)b * CC + c) * NN;
        for (int i = tid; i < NN / 4; i += 256) {
            float4 v = *(const float4*)(row + i * 4);
            s  += v.x + v.y + v.z + v.w;
            s2 += v.x * v.x + v.y * v.y + v.z * v.z + v.w * v.w;
        }
    }
#pragma unroll
    for (int o = 16; o > 0; o >>= 1) {
        s  += __shfl_xor_sync(0xffffffffu, s, o);
        s2 += __shfl_xor_sync(0xffffffffu, s2, o);
    }
    __shared__ float rs[8], rs2[8];
    if ((tid & 31) == 0) { rs[tid >> 5] = s; rs2[tid >> 5] = s2; }
    __syncthreads();
    if (tid == 0) {
        float ts = 0.f, ts2 = 0.f;
        for (int i = 0; i < 8; ++i) { ts += rs[i]; ts2 += rs2[i]; }
        const float cnt = (float)(BB * NN);
        const float mean = ts / cnt;
        const float var = ts2 / cnt - mean * mean;
        s_mean[c] = mean;
        s_rstd[c] = rsqrtf(var + EPSBN);
    }
}

__global__ __launch_bounds__(256) void bn_finalize_kernel(
    const float* __restrict__ wy, const float* __restrict__ x,
    const float* __restrict__ gamma, const float* __restrict__ beta,
    float* __restrict__ out)
{
    const size_t i4 = (size_t)blockIdx.x * 256 + threadIdx.x;
    const size_t total4 = (size_t)BB * CC * NN / 4;
    if (i4 >= total4) return;
    const size_t i = i4 * 4;
    const int c = (int)((i / NN) % CC);
    float4 w  = *(const float4*)(wy + i);
    float4 xv = *(const float4*)(x + i);
    const float m = s_mean[c], r = s_rstd[c];
    const float gm = gamma[c], bt = beta[c];
    float4 o;
    o.x = (w.x - m) * r * gm + bt + xv.x;
    o.y = (w.y - m) * r * gm + bt + xv.y;
    o.z = (w.z - m) * r * gm + bt + xv.z;
    o.w = (w.w - m) * r * gm + bt + xv.w;
    *(float4*)(out + i) = o;
}

// ============================================================================
// Launch
// ============================================================================
extern "C" void kernel_launch(void* const* d_in, const int* in_sizes, int n_in,
                              void* d_out, int out_size)
{
    (void)in_sizes; (void)n_in; (void)out_size;
    const float* x       = (const float*)d_in[0];
    const float* theta_w = (const float*)d_in[1];
    const float* theta_b = (const float*)d_in[2];
    const float* phi_w   = (const float*)d_in[3];
    const float* phi_b   = (const float*)d_in[4];
    const float* g_w     = (const float*)d_in[5];
    const float* g_b     = (const float*)d_in[6];
    const float* w_w     = (const float*)d_in[7];
    const float* w_b     = (const float*)d_in[8];
    const float* gamma   = (const float*)d_in[9];
    const float* beta    = (const float*)d_in[10];
    float* out = (float*)d_out;

    float* p_wy;
    __half *p_xT, *p_thT, *p_phT, *p_gp, *p_y, *p_f, *p_pf;
    __half *p_tw, *p_pw, *p_gw, *p_ww;
    cudaGetSymbolAddress((void**)&p_wy,  s_wy);
    cudaGetSymbolAddress((void**)&p_xT,  g_xT);
    cudaGetSymbolAddress((void**)&p_thT, g_thT);
    cudaGetSymbolAddress((void**)&p_phT, g_phT);
    cudaGetSymbolAddress((void**)&p_gp,  g_gp);
    cudaGetSymbolAddress((void**)&p_y,   g_y);
    cudaGetSymbolAddress((void**)&p_f,   g_f);
    cudaGetSymbolAddress((void**)&p_pf,  g_pf);
    cudaGetSymbolAddress((void**)&p_tw,  g_tw);
    cudaGetSymbolAddress((void**)&p_pw,  g_pw);
    cudaGetSymbolAddress((void**)&p_gw,  g_gw);
    cudaGetSymbolAddress((void**)&p_ww,  g_ww);

    cudaFuncSetAttribute(mma_h1<0, 1>, cudaFuncAttributeMaxDynamicSharedMemorySize, MMA_SMEM1);
    cudaFuncSetAttribute(mma_h1<1, 0>, cudaFuncAttributeMaxDynamicSharedMemorySize, MMA_SMEM1);
    cudaFuncSetAttribute(mma_h1<1, 1>, cudaFuncAttributeMaxDynamicSharedMemorySize, MMA_SMEM1);
    cudaFuncSetAttribute(mma_h1<1, 2>, cudaFuncAttributeMaxDynamicSharedMemorySize, MMA_SMEM1);

    const dim3 blk(256);
    const long long sXT = (long long)NN * CC;
    const long long sP  = (long long)CI * NN;   // == NN*CI
    const long long sF  = (long long)NN * NN;

    // 0) operand conversions (all fp16)
    const dim3 gxT(NN / 32, CC / 32, BB);
    transpose16_kernel<<<gxT, blk>>>(x, p_xT, CC);
    const size_t nw4 = (size_t)CI * CC / 4;
    conv16_kernel<<<(unsigned)((nw4 + 255) / 256), blk>>>(theta_w, p_tw, nw4);
    conv16_kernel<<<(unsigned)((nw4 + 255) / 256), blk>>>(phi_w,   p_pw, nw4);
    conv16_kernel<<<(unsigned)((nw4 + 255) / 256), blk>>>(g_w,     p_gw, nw4);
    conv16_kernel<<<(unsigned)((nw4 + 255) / 256), blk>>>(w_w,     p_ww, nw4);

    // 1) projections (fp16 h1 engine, fp16 out, bias fused)
    const dim3 gth(CI / 128, (NN + 127) / 128, BB);   // (2, 25, 8)
    mma_h1<1, 2><<<gth, blk, MMA_SMEM1>>>(p_xT, p_tw, nullptr, p_thT,
        theta_b, 1.0f, NN, CI, CC, sXT, 0, sP);
    mma_h1<1, 2><<<gth, blk, MMA_SMEM1>>>(p_xT, p_pw, nullptr, p_phT,
        phi_b, 1.0f, NN, CI, CC, sXT, 0, sP);
    const dim3 gg((NN + 127) / 128, CI / 128, BB);    // (25, 2, 8)
    mma_h1<1, 1><<<gg, blk, MMA_SMEM1>>>(p_gw, p_xT, nullptr, p_gp,
        g_b, 1.0f, CI, NN, CC, 0, sXT, sP);

    // 2) f[n][m] = thT[n] . phT[m]   (fp16 out)
    const dim3 gf((NN + 127) / 128, (NN + 127) / 128, BB);   // (25, 25, 8)
    mma_h1<1, 0><<<gf, blk, MMA_SMEM1>>>(p_thT, p_phT, nullptr, p_f,
        nullptr, 1.0f, NN, NN, CI, sP, sP, sF);

    // 3) softmax (fp16 in) -> scaled fp16 probabilities
    softmax_kernel<<<BB * NN, blk>>>(p_f, p_pf);

    // 4) y[n][c] = Pf[n] . g[c]      (fp16 out, /scale)
    const dim3 gy(CI / 128, (NN + 127) / 128, BB);    // (2, 25, 8)
    mma_h1<1, 0><<<gy, blk, MMA_SMEM1>>>(p_pf, p_gp, nullptr, p_y,
        nullptr, 1.0f / PF_SCALE, NN, CI, NN, sF, sP, sP);

    // 5) wy[o][n] = w_w[o] . y[n]    (fp32 out, row bias)
    const dim3 gw((NN + 127) / 128, CC / 128, BB);    // (25, 4, 8)
    mma_h1<0, 1><<<gw, blk, MMA_SMEM1>>>(p_ww, p_y, p_wy, nullptr,
        w_b, 1.0f, CC, NN, CI, 0, sP, (long long)CC * NN);

    // 6) BN stats + finalize with residual
    bnstats_kernel<<<CC, blk>>>(p_wy);
    bn_finalize_kernel<<<(unsigned)((size_t)BB * CC * NN / 4 / 256), blk>>>(p_wy, x, gamma, beta, out);
}